// round 9
// baseline (speedup 1.0000x reference)
#include <cuda_runtime.h>
#include <cuda_bf16.h>
#include <math.h>
#include <stdint.h>

#define BS 128
#define LATENT 512
#define HID 1024
#define G4 4096       // 4*HID
#define KTOT 1536     // LATENT + HID unified K
#define NBLK 128
#define NTHR 512
#define NCHUNK 24     // KTOT / 64
#define CHK 64        // bf16 K elems per chunk (= 128 bytes/row)

typedef unsigned long long u64;
typedef unsigned int u32;

// ---------------- persistent device-global state (no runtime alloc) --------
__device__ __align__(16) __nv_bfloat16 g_Whi[2][G4][KTOT];    // weight hi, gate-interleaved
__device__ __align__(16) __nv_bfloat16 g_Wlo[2][G4][KTOT];    // weight lo
__device__ __align__(16) __nv_bfloat16 g_Ahi[2][2][BS][KTOT]; // [buf][dir][row][k] activation hi
__device__ __align__(16) __nv_bfloat16 g_Alo[2][2][BS][KTOT]; // activation lo
__device__ __align__(16) float g_bias[2][G4];                 // gate-interleaved bias
__device__ __align__(16) float g_h[2][2][BS][HID];            // fp32 h for head [buf][dir]
__device__ __align__(16) float g_c[2][BS][HID];               // cell state [dir]
__device__ u64 g_arrive;                                      // grid barrier counter

// ---------------- helpers --------------------------------------------------
__device__ __forceinline__ void unpack2(u64 v, float& lo, float& hi) {
    asm("mov.b64 {%0, %1}, %2;" : "=f"(lo), "=f"(hi) : "l"(v));
}
__device__ __forceinline__ void fma2(u64& d, u64 a, u64 b) {
    asm("fma.rn.f32x2 %0, %1, %2, %0;" : "+l"(d) : "l"(a), "l"(b));
}
__device__ __forceinline__ u32 smem_u32(const void* p) {
    u32 a; asm("{ .reg .u64 t; cvta.to.shared.u64 t, %1; cvt.u32.u64 %0, t; }" : "=r"(a) : "l"(p));
    return a;
}

#define SW128(x) ((x) ^ (((x) >> 3) & 0x70))

#define CP16(dst, src) \
    asm volatile("cp.async.cg.shared.global [%0], [%1], 16;" :: "r"(dst), "l"(src))
#define CP_COMMIT() asm volatile("cp.async.commit_group;" ::: "memory")
#define CP_WAIT(n)  asm volatile("cp.async.wait_group %0;" :: "n"(n) : "memory")

#define LDSM4(R, A)                                                          \
    asm volatile("ldmatrix.sync.aligned.m8n8.x4.shared.b16 {%0,%1,%2,%3}, [%4];" \
                 : "=r"((R)[0]), "=r"((R)[1]), "=r"((R)[2]), "=r"((R)[3])    \
                 : "r"(A))

#define MMA16816(D, A, B0, B1)                                               \
    asm volatile("mma.sync.aligned.m16n8k16.row.col.f32.bf16.bf16.f32 "      \
                 "{%0,%1,%2,%3}, {%4,%5,%6,%7}, {%8,%9}, {%0,%1,%2,%3};"     \
                 : "+f"((D)[0]), "+f"((D)[1]), "+f"((D)[2]), "+f"((D)[3])    \
                 : "r"((A)[0]), "r"((A)[1]), "r"((A)[2]), "r"((A)[3]),       \
                   "r"(B0), "r"(B1))

// Fence-free grid barrier. Release via atom.add.release.gpu (orders all this
// block's prior write-through STGs at L2, cumulative with the bar.sync).
// Acquire via leader ld.acquire.gpu poll. NO CCTL.IVALL: every cross-block
// read in this kernel bypasses L1 (cp.async.cg / __ldcg), so stale L1 lines
// are impossible; block-private and read-only data may stay L1-resident.
__device__ __forceinline__ void grid_sync(u64 target) {
    __syncthreads();
    if (threadIdx.x == 0) {
        u64 old;
        asm volatile("atom.add.release.gpu.u64 %0, [%1], 1;"
                     : "=l"(old) : "l"(&g_arrive) : "memory");
        u64 v;
        do {
            asm volatile("ld.acquire.gpu.u64 %0, [%1];"
                         : "=l"(v) : "l"(&g_arrive) : "memory");
        } while (v < target);
    }
    __syncthreads();
}

// smem: 3 stages of 48 KB. Stage layout: Ah 16K | Al 16K | Wh 8K | Wl 8K
#define STG    49152
#define OFF_AL 16384
#define OFF_WH 32768
#define OFF_WL 40960
#define DYN_SMEM (3 * STG)

// ---------------------------------------------------------------------------
// prep: gate-interleave + bf16-split weights into unified-K layout; init
// activations buf0 (x part = decoder_input, h part = 0), h, c, barrier.
// reordered row r -> orig row (r&3)*HID + (r>>2); K: [0,512)=Wih, [512,1536)=Whh
// ---------------------------------------------------------------------------
__global__ void prep_kernel(const float* __restrict__ Wih_f, const float* __restrict__ Whh_f,
                            const float* __restrict__ b_f,
                            const float* __restrict__ Wih_b, const float* __restrict__ Whh_b,
                            const float* __restrict__ b_b,
                            const float* __restrict__ dec) {
    int idx = blockIdx.x * blockDim.x + threadIdx.x;
    int stride = gridDim.x * blockDim.x;
    if (idx == 0) g_arrive = 0ULL;

    for (int i = idx; i < 2 * G4 * KTOT; i += stride) {
        int dir = i / (G4 * KTOT);
        int rem = i - dir * (G4 * KTOT);
        int r = rem / KTOT, k = rem - r * KTOT;
        int orow = (r & 3) * HID + (r >> 2);
        float w;
        if (k < LATENT) w = (dir ? Wih_b : Wih_f)[orow * LATENT + k];
        else            w = (dir ? Whh_b : Whh_f)[orow * HID + (k - LATENT)];
        __nv_bfloat16 hi = __float2bfloat16_rn(w);
        __nv_bfloat16 lo = __float2bfloat16_rn(w - __bfloat162float(hi));
        g_Whi[dir][r][k] = hi;
        g_Wlo[dir][r][k] = lo;
    }
    for (int i = idx; i < 2 * G4; i += stride) {
        int dir = i / G4, r = i - dir * G4;
        g_bias[dir][r] = (dir ? b_b : b_f)[(r & 3) * HID + (r >> 2)];
    }
    for (int i = idx; i < 2 * 2 * BS * KTOT; i += stride) {
        int buf = i / (2 * BS * KTOT);
        int rem = i - buf * (2 * BS * KTOT);
        int dir = rem / (BS * KTOT);
        int rem2 = rem - dir * (BS * KTOT);
        int row = rem2 / KTOT, k = rem2 - row * KTOT;
        float v = (buf == 0 && k < LATENT) ? dec[row * LATENT + k] : 0.f;
        __nv_bfloat16 hi = __float2bfloat16_rn(v);
        __nv_bfloat16 lo = __float2bfloat16_rn(v - __bfloat162float(hi));
        g_Ahi[buf][dir][row][k] = hi;
        g_Alo[buf][dir][row][k] = lo;
    }
    for (int i = idx; i < 2 * 2 * BS * HID; i += stride) ((float*)g_h)[i] = 0.f;
    for (int i = idx; i < 2 * BS * HID; i += stride)     ((float*)g_c)[i] = 0.f;
}

// ---------------------------------------------------------------------------
// persistent kernel: 128 blocks x 512 threads (16 warps), one launch, all T.
// phase A: block = (dir, 64 gate-cols); 4x4 warp grid, warp tile 32(M)x16(N).
//          bf16 3-split mma.sync HMMA; cp.async 3-stage ring, depth-1.
// phase B: head (x_next GEMM + fc1), FFMA2.
// ---------------------------------------------------------------------------
__global__ void __launch_bounds__(NTHR, 1) lstm_persist(
        int T, float* __restrict__ out,
        const float* __restrict__ W_out, const float* __restrict__ b_out,
        const float* __restrict__ W_fc1, const float* __restrict__ b_fc1) {

    extern __shared__ __align__(16) unsigned char dsm[];
    const u32 smem_base = smem_u32(dsm);

    const int tid = threadIdx.x;
    const int bid = blockIdx.x;
    const int wid = tid >> 5;
    const int lane = tid & 31;

    const int dir = bid >> 6;
    const int colbase = (bid & 63) << 6;

    // warp tile mapping: 4 warps along M (32 rows), 4 along N (16 cols)
    const int wm = wid & 3;
    const int wn = wid >> 2;
    const int R0 = wm * 32;
    const int C0 = wn * 16;

    // ldmatrix per-lane constants
    const int arow = lane & 15;                          // A: m16 row within tile
    const u32 khA = (u32)(lane >> 4) * 16;               // A: k-half byte offset
    const int brow = (lane & 7) + ((lane >> 4) & 1) * 8; // B: n row within n16
    const u32 khB = (u32)((lane >> 3) & 1) * 16;         // B: k-half byte offset
    const u32 swA = (u32)(arow & 7) << 4;
    const u32 swB = (u32)(brow & 7) << 4;
    // stage-relative byte offsets of the ldmatrix base rows
    const u32 aRowOff0 = (u32)(R0 + arow) * 128;
    const u32 aRowOff1 = (u32)(R0 + 16 + arow) * 128;
    const u32 bRowOff0 = OFF_WH + (u32)(C0 + brow) * 128;

    // cp.async per-thread source/dest precompute (512 threads):
    // A hi/lo: 1024 x 16B each -> 2 per thread; W hi/lo: 512 x 16B -> 1 per thread
    u32 cpdstA[2], cpdstW;
    int cprowA[2], cpqA[2], cprowW, cpqW;
#pragma unroll
    for (int i = 0; i < 2; i++) {
        int p = tid + i * NTHR, row = p >> 3, q = p & 7;
        cprowA[i] = row; cpqA[i] = q;
        cpdstA[i] = SW128((u32)(row * 128 + q * 16));
    }
    {
        int row = tid >> 3, q = tid & 7;
        cprowW = row; cpqW = q;
        cpdstW = SW128((u32)(row * 128 + q * 16));
    }

    // head mapping
    const int bt = bid >> 3;   // 16 row-tiles of 8
    const int lt = bid & 7;    // 8 latent col-tiles of 64
    float (*s_hb)[HID] = (float (*)[HID])dsm;

    u64 nbar = 0;

    for (int t = 0; t < T; t++) {
        const int cur = t & 1;
        const int nxt = cur ^ 1;
        const __nv_bfloat16* __restrict__ Ah = &g_Ahi[cur][dir][0][0];
        const __nv_bfloat16* __restrict__ Al = &g_Alo[cur][dir][0][0];
        const __nv_bfloat16* __restrict__ Wh = &g_Whi[dir][colbase][0];
        const __nv_bfloat16* __restrict__ Wl = &g_Wlo[dir][colbase][0];

#define ISSUE_CHUNK(cc, st)                                                   \
        {                                                                      \
            const u32 sb = smem_base + (u32)(st) * STG;                        \
            const size_t c64 = (size_t)(cc) * CHK;                             \
            _Pragma("unroll")                                                  \
            for (int i = 0; i < 2; i++) {                                      \
                const char* s  = (const char*)(Ah + (size_t)cprowA[i] * KTOT + c64) + cpqA[i] * 16; \
                const char* s2 = (const char*)(Al + (size_t)cprowA[i] * KTOT + c64) + cpqA[i] * 16; \
                CP16(sb + cpdstA[i], s);                                       \
                CP16(sb + OFF_AL + cpdstA[i], s2);                             \
            }                                                                  \
            {                                                                  \
                const char* s  = (const char*)(Wh + (size_t)cprowW * KTOT + c64) + cpqW * 16; \
                const char* s2 = (const char*)(Wl + (size_t)cprowW * KTOT + c64) + cpqW * 16; \
                CP16(sb + OFF_WH + cpdstW, s);                                 \
                CP16(sb + OFF_WL + cpdstW, s2);                                \
            }                                                                  \
            CP_COMMIT();                                                       \
        }

        // ================= phase A: bf16-split HMMA pipeline ===============
        float acc[2][2][4];
#pragma unroll
        for (int mt = 0; mt < 2; mt++)
#pragma unroll
            for (int nt = 0; nt < 2; nt++)
#pragma unroll
                for (int i = 0; i < 4; i++) acc[mt][nt][i] = 0.f;

        ISSUE_CHUNK(0, 0);

        int stage = 0;
#pragma unroll 1
        for (int c = 0; c < NCHUNK; c++) {
            if (c + 1 < NCHUNK) {
                const int nstage = (stage == 2) ? 0 : stage + 1;
                ISSUE_CHUNK(c + 1, nstage);
                CP_WAIT(1);          // chunk c complete (c+1 may be in flight)
            } else {
                CP_WAIT(0);
            }
            __syncthreads();         // chunk c visible; ring period 3 protects reuse

            const u32 sb = smem_base + (u32)stage * STG;
            const u32 a0 = sb + aRowOff0, a1 = sb + aRowOff1;
            const u32 b0 = sb + bRowOff0;

#pragma unroll
            for (int kk = 0; kk < 4; kk++) {
                const u32 xA = ((u32)(kk * 32) + khA) ^ swA;
                const u32 xB = ((u32)(kk * 32) + khB) ^ swB;
                u32 ah[2][4], al[2][4], bh[4], bl[4];
                LDSM4(ah[0], a0 + xA);
                LDSM4(ah[1], a1 + xA);
                LDSM4(al[0], a0 + OFF_AL + xA);
                LDSM4(al[1], a1 + OFF_AL + xA);
                LDSM4(bh, b0 + xB);
                LDSM4(bl, b0 + (OFF_WL - OFF_WH) + xB);
#pragma unroll
                for (int mt = 0; mt < 2; mt++)
#pragma unroll
                    for (int hf = 0; hf < 2; hf++) {
                        MMA16816(acc[mt][hf], ah[mt], bh[2 * hf], bh[2 * hf + 1]);
                        MMA16816(acc[mt][hf], ah[mt], bl[2 * hf], bl[2 * hf + 1]);
                        MMA16816(acc[mt][hf], al[mt], bh[2 * hf], bh[2 * hf + 1]);
                    }
            }
            stage = (stage == 2) ? 0 : stage + 1;
        }

        // -------- epilogue: pair-exchange quads, LSTM cell, write h --------
#pragma unroll
        for (int mt = 0; mt < 2; mt++)
#pragma unroll
            for (int nt = 0; nt < 2; nt++) {
                float d0 = acc[mt][nt][0], d1 = acc[mt][nt][1];
                float d2 = acc[mt][nt][2], d3 = acc[mt][nt][3];
                float p0 = __shfl_xor_sync(0xffffffffu, d0, 1);
                float p1 = __shfl_xor_sync(0xffffffffu, d1, 1);
                float p2 = __shfl_xor_sync(0xffffffffu, d2, 1);
                float p3 = __shfl_xor_sync(0xffffffffu, d3, 1);
                if (!(lane & 1)) {
                    const int q = (lane >> 1) & 1;
                    const int col4 = colbase + C0 + nt * 8 + q * 4;
                    const int jp = col4 >> 2;
                    const float4 b4 = *(const float4*)&g_bias[dir][col4];
                    const int r0 = R0 + mt * 16 + (lane >> 2);
#pragma unroll
                    for (int rr = 0; rr < 2; rr++) {
                        const int row = r0 + rr * 8;
                        float zi = (rr ? d2 : d0) + b4.x;
                        float zf = (rr ? d3 : d1) + b4.y;
                        float zg = (rr ? p2 : p0) + b4.z;
                        float zo = (rr ? p3 : p1) + b4.w;
                        float si = 1.f / (1.f + expf(-zi));
                        float sf = 1.f / (1.f + expf(-zf));
                        float so = 1.f / (1.f + expf(-zo));
                        float c2 = sf * g_c[dir][row][jp] + si * tanhf(zg);
                        g_c[dir][row][jp] = c2;
                        float hv = so * tanhf(c2);
                        g_h[nxt][dir][row][jp] = hv;
                        __nv_bfloat16 hhi = __float2bfloat16_rn(hv);
                        __nv_bfloat16 hlo = __float2bfloat16_rn(hv - __bfloat162float(hhi));
                        g_Ahi[nxt][dir][row][LATENT + jp] = hhi;
                        g_Alo[nxt][dir][row][LATENT + jp] = hlo;
                    }
                }
            }

        nbar++; grid_sync(nbar * NBLK);

        // ================= phase B: head ===================================
        // stage hb rows bt*8..+7 into smem (L2-direct: cross-block data)
        for (int i = tid; i < 8 * HID / 4; i += NTHR) {
            int r = i >> 8;               // 256 float4 per row
            int k = (i & 255) * 4;
            const float4* src = (const float4*)&g_h[nxt][1][bt * 8 + r][k];
            *(float4*)&s_hb[r][k] = __ldcg(src);
        }
        __syncthreads();

        // x_next = hb @ W_out^T + b_out, split to bf16 hi/lo for both dirs
        {
            const int l_loc = tid >> 3;   // 0..63
            const int q = tid & 7;        // 0..7, 8-way K split
            const int l = lt * 64 + l_loc;
            const u64* __restrict__ wp = (const u64*)(W_out + (size_t)l * HID) + q * 64;
            const u64* __restrict__ hp = (const u64*)&s_hb[0][0] + q * 64;
            u64 hacc[8];
#pragma unroll
            for (int r = 0; r < 8; r++) hacc[r] = 0ull;
#pragma unroll 2
            for (int k2 = 0; k2 < 64; k2++) {
                u64 w = wp[k2];
#pragma unroll
                for (int r = 0; r < 8; r++) fma2(hacc[r], w, hp[r * 512 + k2]);
            }
#pragma unroll
            for (int r = 0; r < 8; r++) {
                float lo, hi; unpack2(hacc[r], lo, hi);
                float s = lo + hi;
                s += __shfl_xor_sync(0xffffffffu, s, 1);
                s += __shfl_xor_sync(0xffffffffu, s, 2);
                s += __shfl_xor_sync(0xffffffffu, s, 4);
                if (q == 0) {
                    float xv = s + b_out[l];
                    int row = bt * 8 + r;
                    __nv_bfloat16 xh = __float2bfloat16_rn(xv);
                    __nv_bfloat16 xl = __float2bfloat16_rn(xv - __bfloat162float(xh));
                    g_Ahi[nxt][0][row][l] = xh;
                    g_Ahi[nxt][1][row][l] = xh;
                    g_Alo[nxt][0][row][l] = xl;
                    g_Alo[nxt][1][row][l] = xl;
                }
            }
        }

        // out[b, t] = relu(concat(hf,hb)) . W_fc1 + b_fc1   (lt==0 blocks)
        if (lt == 0 && tid < 256) {
            const int r = tid >> 5, ln = tid & 31;
            const int b = bt * 8 + r;
            const float* __restrict__ hf = &g_h[nxt][0][b][0];
            float facc = 0.f;
            for (int k = ln * 4; k < HID; k += 128) {
                float4 f   = __ldcg((const float4*)&hf[k]);
                float4 wf  = *(const float4*)&W_fc1[k];
                float4 hb4 = *(const float4*)&s_hb[r][k];
                float4 wb  = *(const float4*)&W_fc1[HID + k];
                facc += fmaxf(f.x, 0.f) * wf.x + fmaxf(f.y, 0.f) * wf.y
                      + fmaxf(f.z, 0.f) * wf.z + fmaxf(f.w, 0.f) * wf.w
                      + fmaxf(hb4.x, 0.f) * wb.x + fmaxf(hb4.y, 0.f) * wb.y
                      + fmaxf(hb4.z, 0.f) * wb.z + fmaxf(hb4.w, 0.f) * wb.w;
            }
#pragma unroll
            for (int off = 16; off; off >>= 1)
                facc += __shfl_xor_sync(0xffffffffu, facc, off);
            if (ln == 0) out[(size_t)b * T + t] = facc + b_fc1[0];
        }

        nbar++; grid_sync(nbar * NBLK);
    }
}

// ---------------------------------------------------------------------------
extern "C" void kernel_launch(void* const* d_in, const int* in_sizes, int n_in,
                              void* d_out, int out_size) {
    const float* dec   = (const float*)d_in[0];
    // d_in[1] = lengths (T derives from out_size)
    const float* Wih_f = (const float*)d_in[2];
    const float* Whh_f = (const float*)d_in[3];
    const float* b_f   = (const float*)d_in[4];
    const float* Wih_b = (const float*)d_in[5];
    const float* Whh_b = (const float*)d_in[6];
    const float* b_b   = (const float*)d_in[7];
    const float* W_out = (const float*)d_in[8];
    const float* b_out = (const float*)d_in[9];
    const float* W_fc1 = (const float*)d_in[10];
    const float* b_fc1 = (const float*)d_in[11];
    float* out = (float*)d_out;

    const int T = out_size / BS;

    cudaFuncSetAttribute(lstm_persist, cudaFuncAttributeMaxDynamicSharedMemorySize, DYN_SMEM);

    prep_kernel<<<1024, 256>>>(Wih_f, Whh_f, b_f, Wih_b, Whh_b, b_b, dec);
    if (T > 0) {
        lstm_persist<<<NBLK, NTHR, DYN_SMEM>>>(T, out, W_out, b_out, W_fc1, b_fc1);
    }
}

// round 10
// speedup vs baseline: 1.3372x; 1.3372x over previous
#include <cuda_runtime.h>
#include <cuda_bf16.h>
#include <math.h>
#include <stdint.h>

#define BS 128
#define LATENT 512
#define HID 1024
#define G4 4096       // 4*HID
#define KTOT 1536     // LATENT + HID unified K
#define NBLK 128
#define NTHR 256
#define NCHUNK 24     // KTOT / 64
#define CHK 64        // bf16 K elems per chunk (= 128 bytes/row)

typedef unsigned long long u64;
typedef unsigned int u32;

// ---------------- persistent device-global state (no runtime alloc) --------
__device__ __align__(16) __nv_bfloat16 g_Whi[2][G4][KTOT];    // weight hi, gate-interleaved
__device__ __align__(16) __nv_bfloat16 g_Wlo[2][G4][KTOT];    // weight lo
__device__ __align__(16) __nv_bfloat16 g_Ahi[2][2][BS][KTOT]; // [buf][dir][row][k] activation hi
__device__ __align__(16) __nv_bfloat16 g_Alo[2][2][BS][KTOT]; // activation lo
__device__ __align__(16) float g_bias[2][G4];                 // gate-interleaved bias
__device__ __align__(16) float g_h[2][2][BS][HID];            // fp32 h for head [buf][dir]
__device__ __align__(16) float g_c[2][BS][HID];               // cell state [dir]
__device__ u64 g_arrive;                                      // grid barrier counter

// ---------------- helpers --------------------------------------------------
__device__ __forceinline__ void unpack2(u64 v, float& lo, float& hi) {
    asm("mov.b64 {%0, %1}, %2;" : "=f"(lo), "=f"(hi) : "l"(v));
}
__device__ __forceinline__ void fma2(u64& d, u64 a, u64 b) {
    asm("fma.rn.f32x2 %0, %1, %2, %0;" : "+l"(d) : "l"(a), "l"(b));
}
__device__ __forceinline__ u32 smem_u32(const void* p) {
    u32 a; asm("{ .reg .u64 t; cvta.to.shared.u64 t, %1; cvt.u32.u64 %0, t; }" : "=r"(a) : "l"(p));
    return a;
}

#define SW128(x) ((x) ^ (((x) >> 3) & 0x70))

#define CP16(dst, src) \
    asm volatile("cp.async.cg.shared.global [%0], [%1], 16;" :: "r"(dst), "l"(src))
#define CP_COMMIT() asm volatile("cp.async.commit_group;" ::: "memory")
#define CP_WAIT(n)  asm volatile("cp.async.wait_group %0;" :: "n"(n) : "memory")

#define LDSM4(R, A)                                                          \
    asm volatile("ldmatrix.sync.aligned.m8n8.x4.shared.b16 {%0,%1,%2,%3}, [%4];" \
                 : "=r"((R)[0]), "=r"((R)[1]), "=r"((R)[2]), "=r"((R)[3])    \
                 : "r"(A))

#define MMA16816(D, A, B0, B1)                                               \
    asm volatile("mma.sync.aligned.m16n8k16.row.col.f32.bf16.bf16.f32 "      \
                 "{%0,%1,%2,%3}, {%4,%5,%6,%7}, {%8,%9}, {%0,%1,%2,%3};"     \
                 : "+f"((D)[0]), "+f"((D)[1]), "+f"((D)[2]), "+f"((D)[3])    \
                 : "r"((A)[0]), "r"((A)[1]), "r"((A)[2]), "r"((A)[3]),       \
                   "r"(B0), "r"(B1))

// Fence-free grid barrier. Release via atom.add.release.gpu (orders this
// block's prior global stores at L2 — L1 is write-through, so the data is
// in L2 before the release). Acquire via leader ld.acquire.gpu poll.
// NO CCTL.IVALL: every cross-block read in this kernel bypasses L1
// (cp.async.cg / __ldcg), so stale L1 lines are impossible; block-private
// (g_c) and read-only (g_bias, weights) data stays L1-resident across steps.
__device__ __forceinline__ void grid_sync(u64 target) {
    __syncthreads();
    if (threadIdx.x == 0) {
        u64 old;
        asm volatile("atom.add.release.gpu.u64 %0, [%1], 1;"
                     : "=l"(old) : "l"(&g_arrive) : "memory");
        u64 v;
        do {
            asm volatile("ld.acquire.gpu.u64 %0, [%1];"
                         : "=l"(v) : "l"(&g_arrive) : "memory");
        } while (v < target);
    }
    __syncthreads();
}

// fast nonlinearities (MUFU-based; rel err ~1e-6, safe vs 1e-3 threshold)
__device__ __forceinline__ float fast_sigmoid(float x) {
    return __fdividef(1.f, 1.f + __expf(-x));
}
__device__ __forceinline__ float fast_tanh(float x) {
    return 1.f - __fdividef(2.f, 1.f + __expf(2.f * x));
}

// smem: 3 stages of 48 KB. Stage layout: Ah 16K | Al 16K | Wh 8K | Wl 8K
#define STG    49152
#define OFF_AL 16384
#define OFF_WH 32768
#define OFF_WL 40960
#define DYN_SMEM (3 * STG)

// ---------------------------------------------------------------------------
// prep: gate-interleave + bf16-split weights into unified-K layout; init
// activations buf0 (x part = decoder_input, h part = 0), h, c, barrier.
// reordered row r -> orig row (r&3)*HID + (r>>2); K: [0,512)=Wih, [512,1536)=Whh
// ---------------------------------------------------------------------------
__global__ void prep_kernel(const float* __restrict__ Wih_f, const float* __restrict__ Whh_f,
                            const float* __restrict__ b_f,
                            const float* __restrict__ Wih_b, const float* __restrict__ Whh_b,
                            const float* __restrict__ b_b,
                            const float* __restrict__ dec) {
    int idx = blockIdx.x * blockDim.x + threadIdx.x;
    int stride = gridDim.x * blockDim.x;
    if (idx == 0) g_arrive = 0ULL;

    for (int i = idx; i < 2 * G4 * KTOT; i += stride) {
        int dir = i / (G4 * KTOT);
        int rem = i - dir * (G4 * KTOT);
        int r = rem / KTOT, k = rem - r * KTOT;
        int orow = (r & 3) * HID + (r >> 2);
        float w;
        if (k < LATENT) w = (dir ? Wih_b : Wih_f)[orow * LATENT + k];
        else            w = (dir ? Whh_b : Whh_f)[orow * HID + (k - LATENT)];
        __nv_bfloat16 hi = __float2bfloat16_rn(w);
        __nv_bfloat16 lo = __float2bfloat16_rn(w - __bfloat162float(hi));
        g_Whi[dir][r][k] = hi;
        g_Wlo[dir][r][k] = lo;
    }
    for (int i = idx; i < 2 * G4; i += stride) {
        int dir = i / G4, r = i - dir * G4;
        g_bias[dir][r] = (dir ? b_b : b_f)[(r & 3) * HID + (r >> 2)];
    }
    for (int i = idx; i < 2 * 2 * BS * KTOT; i += stride) {
        int buf = i / (2 * BS * KTOT);
        int rem = i - buf * (2 * BS * KTOT);
        int dir = rem / (BS * KTOT);
        int rem2 = rem - dir * (BS * KTOT);
        int row = rem2 / KTOT, k = rem2 - row * KTOT;
        float v = (buf == 0 && k < LATENT) ? dec[row * LATENT + k] : 0.f;
        __nv_bfloat16 hi = __float2bfloat16_rn(v);
        __nv_bfloat16 lo = __float2bfloat16_rn(v - __bfloat162float(hi));
        g_Ahi[buf][dir][row][k] = hi;
        g_Alo[buf][dir][row][k] = lo;
    }
    for (int i = idx; i < 2 * 2 * BS * HID; i += stride) ((float*)g_h)[i] = 0.f;
    for (int i = idx; i < 2 * BS * HID; i += stride)     ((float*)g_c)[i] = 0.f;
}

// ---------------------------------------------------------------------------
// persistent kernel: 128 blocks x 256 threads, one launch for all T steps.
// phase A: block = (dir, 64 gate-cols); 4x2 warp grid, warp tile 32(M)x32(N).
//          bf16 3-split mma.sync HMMA; cp.async 3-stage ring, depth-1.
// phase B: head (x_next GEMM + fc1), FFMA2.
// ---------------------------------------------------------------------------
__global__ void __launch_bounds__(NTHR, 1) lstm_persist(
        int T, float* __restrict__ out,
        const float* __restrict__ W_out, const float* __restrict__ b_out,
        const float* __restrict__ W_fc1, const float* __restrict__ b_fc1) {

    extern __shared__ __align__(16) unsigned char dsm[];
    const u32 smem_base = smem_u32(dsm);

    const int tid = threadIdx.x;
    const int bid = blockIdx.x;
    const int wid = tid >> 5;
    const int lane = tid & 31;

    const int dir = bid >> 6;
    const int colbase = (bid & 63) << 6;

    // warp tile mapping: 4 warps along M (32 rows), 2 along N (32 cols)
    const int wm = wid & 3;
    const int wn = wid >> 2;
    const int R0 = wm * 32;
    const int C0 = wn * 32;

    // ldmatrix per-lane constants
    const int arow = lane & 15;                          // A: m16 row within tile
    const u32 khA = (u32)(lane >> 4) * 16;               // A: k-half byte offset
    const int brow = (lane & 7) + ((lane >> 4) & 1) * 8; // B: n row within n16 pair
    const u32 khB = (u32)((lane >> 3) & 1) * 16;         // B: k-half byte offset
    const u32 swA = (u32)(arow & 7) << 4;
    const u32 swB = (u32)(brow & 7) << 4;
    // stage-relative byte offsets of the ldmatrix base rows
    const u32 aRowOff0 = (u32)(R0 + arow) * 128;
    const u32 aRowOff1 = (u32)(R0 + 16 + arow) * 128;
    const u32 bRowOff0 = OFF_WH + (u32)(C0 + brow) * 128;
    const u32 bRowOff1 = OFF_WH + (u32)(C0 + 16 + brow) * 128;

    // cp.async per-thread source/dest precompute
    u32 cpdst[6];   // stage-relative swizzled offsets (4 A rows + 2 W rows)
    int cprowA[4], cprowW[2], cpq[6];
#pragma unroll
    for (int i = 0; i < 4; i++) {
        int p = tid + i * NTHR, row = p >> 3, q = p & 7;
        cprowA[i] = row; cpq[i] = q;
        cpdst[i] = SW128((u32)(row * 128 + q * 16));
    }
#pragma unroll
    for (int i = 0; i < 2; i++) {
        int p = tid + i * NTHR, row = p >> 3, q = p & 7;
        cprowW[i] = row; cpq[4 + i] = q;
        cpdst[4 + i] = SW128((u32)(row * 128 + q * 16));
    }

    // head mapping
    const int bt = bid >> 3;   // 16 row-tiles of 8
    const int lt = bid & 7;    // 8 latent col-tiles of 64
    float (*s_hb)[HID] = (float (*)[HID])dsm;

    u64 nbar = 0;

    for (int t = 0; t < T; t++) {
        const int cur = t & 1;
        const int nxt = cur ^ 1;
        const __nv_bfloat16* __restrict__ Ah = &g_Ahi[cur][dir][0][0];
        const __nv_bfloat16* __restrict__ Al = &g_Alo[cur][dir][0][0];
        const __nv_bfloat16* __restrict__ Wh = &g_Whi[dir][colbase][0];
        const __nv_bfloat16* __restrict__ Wl = &g_Wlo[dir][colbase][0];

#define ISSUE_CHUNK(cc, st)                                                   \
        {                                                                      \
            const u32 sb = smem_base + (u32)(st) * STG;                        \
            const size_t c64 = (size_t)(cc) * CHK;                             \
            _Pragma("unroll")                                                  \
            for (int i = 0; i < 4; i++) {                                      \
                const char* s  = (const char*)(Ah + (size_t)cprowA[i] * KTOT + c64) + cpq[i] * 16; \
                const char* s2 = (const char*)(Al + (size_t)cprowA[i] * KTOT + c64) + cpq[i] * 16; \
                CP16(sb + cpdst[i], s);                                        \
                CP16(sb + OFF_AL + cpdst[i], s2);                              \
            }                                                                  \
            _Pragma("unroll")                                                  \
            for (int i = 0; i < 2; i++) {                                      \
                const char* s  = (const char*)(Wh + (size_t)cprowW[i] * KTOT + c64) + cpq[4 + i] * 16; \
                const char* s2 = (const char*)(Wl + (size_t)cprowW[i] * KTOT + c64) + cpq[4 + i] * 16; \
                CP16(sb + OFF_WH + cpdst[4 + i], s);                           \
                CP16(sb + OFF_WL + cpdst[4 + i], s2);                          \
            }                                                                  \
            CP_COMMIT();                                                       \
        }

        // ================= phase A: bf16-split HMMA pipeline ===============
        float acc[2][4][4];
#pragma unroll
        for (int mt = 0; mt < 2; mt++)
#pragma unroll
            for (int nt = 0; nt < 4; nt++)
#pragma unroll
                for (int i = 0; i < 4; i++) acc[mt][nt][i] = 0.f;

        ISSUE_CHUNK(0, 0);

        int stage = 0;
#pragma unroll 1
        for (int c = 0; c < NCHUNK; c++) {
            if (c + 1 < NCHUNK) {
                const int nstage = (stage == 2) ? 0 : stage + 1;
                ISSUE_CHUNK(c + 1, nstage);
                CP_WAIT(1);          // chunk c complete (c+1 may be in flight)
            } else {
                CP_WAIT(0);
            }
            __syncthreads();         // chunk c visible; ring period 3 protects reuse

            const u32 sb = smem_base + (u32)stage * STG;
            const u32 a0 = sb + aRowOff0, a1 = sb + aRowOff1;
            const u32 b0 = sb + bRowOff0, b1 = sb + bRowOff1;

#pragma unroll
            for (int kk = 0; kk < 4; kk++) {
                const u32 xA = ((u32)(kk * 32) + khA) ^ swA;
                const u32 xB = ((u32)(kk * 32) + khB) ^ swB;
                u32 ah[2][4], al[2][4], bh[2][4], bl[2][4];
                LDSM4(ah[0], a0 + xA);
                LDSM4(ah[1], a1 + xA);
                LDSM4(al[0], a0 + OFF_AL + xA);
                LDSM4(al[1], a1 + OFF_AL + xA);
                LDSM4(bh[0], b0 + xB);
                LDSM4(bh[1], b1 + xB);
                LDSM4(bl[0], b0 + (OFF_WL - OFF_WH) + xB);
                LDSM4(bl[1], b1 + (OFF_WL - OFF_WH) + xB);
#pragma unroll
                for (int mt = 0; mt < 2; mt++)
#pragma unroll
                    for (int np = 0; np < 2; np++)
#pragma unroll
                        for (int hf = 0; hf < 2; hf++) {
                            const int nt = np * 2 + hf;
                            MMA16816(acc[mt][nt], ah[mt], bh[np][2 * hf], bh[np][2 * hf + 1]);
                            MMA16816(acc[mt][nt], ah[mt], bl[np][2 * hf], bl[np][2 * hf + 1]);
                            MMA16816(acc[mt][nt], al[mt], bh[np][2 * hf], bh[np][2 * hf + 1]);
                        }
            }
            stage = (stage == 2) ? 0 : stage + 1;
        }

        // -------- epilogue: pair-exchange quads, LSTM cell, write h --------
#pragma unroll
        for (int mt = 0; mt < 2; mt++)
#pragma unroll
            for (int nt = 0; nt < 4; nt++) {
                float d0 = acc[mt][nt][0], d1 = acc[mt][nt][1];
                float d2 = acc[mt][nt][2], d3 = acc[mt][nt][3];
                float p0 = __shfl_xor_sync(0xffffffffu, d0, 1);
                float p1 = __shfl_xor_sync(0xffffffffu, d1, 1);
                float p2 = __shfl_xor_sync(0xffffffffu, d2, 1);
                float p3 = __shfl_xor_sync(0xffffffffu, d3, 1);
                if (!(lane & 1)) {
                    const int q = (lane >> 1) & 1;
                    const int col4 = colbase + C0 + nt * 8 + q * 4;
                    const int jp = col4 >> 2;
                    const float4 b4 = *(const float4*)&g_bias[dir][col4];
                    const int r0 = R0 + mt * 16 + (lane >> 2);
#pragma unroll
                    for (int rr = 0; rr < 2; rr++) {
                        const int row = r0 + rr * 8;
                        float zi = (rr ? d2 : d0) + b4.x;
                        float zf = (rr ? d3 : d1) + b4.y;
                        float zg = (rr ? p2 : p0) + b4.z;
                        float zo = (rr ? p3 : p1) + b4.w;
                        float si = fast_sigmoid(zi);
                        float sf = fast_sigmoid(zf);
                        float so = fast_sigmoid(zo);
                        float c2 = sf * g_c[dir][row][jp] + si * fast_tanh(zg);
                        g_c[dir][row][jp] = c2;
                        float hv = so * fast_tanh(c2);
                        g_h[nxt][dir][row][jp] = hv;
                        __nv_bfloat16 hhi = __float2bfloat16_rn(hv);
                        __nv_bfloat16 hlo = __float2bfloat16_rn(hv - __bfloat162float(hhi));
                        g_Ahi[nxt][dir][row][LATENT + jp] = hhi;
                        g_Alo[nxt][dir][row][LATENT + jp] = hlo;
                    }
                }
            }

        nbar++; grid_sync(nbar * NBLK);

        // ================= phase B: head ===================================
        // stage hb rows bt*8..+7 into smem (L2-direct: written by other blocks)
        for (int i = tid; i < 8 * HID / 4; i += NTHR) {
            int r = i >> 8;               // 256 float4 per row
            int k = (i & 255) * 4;
            *(float4*)&s_hb[r][k] = __ldcg((const float4*)&g_h[nxt][1][bt * 8 + r][k]);
        }
        __syncthreads();

        // x_next = hb @ W_out^T + b_out, split to bf16 hi/lo for both dirs
        {
            const int l_loc = tid >> 2;
            const int q = tid & 3;
            const int l = lt * 64 + l_loc;
            const u64* __restrict__ wp = (const u64*)(W_out + (size_t)l * HID + q * 256);
            const u64* __restrict__ hp = (const u64*)&s_hb[0][q * 256];
            u64 hacc[8];
#pragma unroll
            for (int r = 0; r < 8; r++) hacc[r] = 0ull;
#pragma unroll 2
            for (int k2 = 0; k2 < 128; k2++) {
                u64 w = wp[k2];
#pragma unroll
                for (int r = 0; r < 8; r++) fma2(hacc[r], w, hp[r * 512 + k2]);
            }
#pragma unroll
            for (int r = 0; r < 8; r++) {
                float lo, hi; unpack2(hacc[r], lo, hi);
                float s = lo + hi;
                s += __shfl_xor_sync(0xffffffffu, s, 1);
                s += __shfl_xor_sync(0xffffffffu, s, 2);
                if (q == 0) {
                    float xv = s + b_out[l];
                    int row = bt * 8 + r;
                    __nv_bfloat16 xh = __float2bfloat16_rn(xv);
                    __nv_bfloat16 xl = __float2bfloat16_rn(xv - __bfloat162float(xh));
                    g_Ahi[nxt][0][row][l] = xh;
                    g_Ahi[nxt][1][row][l] = xh;
                    g_Alo[nxt][0][row][l] = xl;
                    g_Alo[nxt][1][row][l] = xl;
                }
            }
        }

        // out[b, t] = relu(concat(hf,hb)) . W_fc1 + b_fc1   (lt==0 blocks)
        if (lt == 0) {
            const int r = tid >> 5, ln = tid & 31;
            const int b = bt * 8 + r;
            const float* __restrict__ hf = &g_h[nxt][0][b][0];
            float facc = 0.f;
            for (int k = ln * 4; k < HID; k += 128) {
                float4 f   = __ldcg((const float4*)&hf[k]);
                float4 wf  = *(const float4*)&W_fc1[k];
                float4 hb4 = *(const float4*)&s_hb[r][k];
                float4 wb  = *(const float4*)&W_fc1[HID + k];
                facc += fmaxf(f.x, 0.f) * wf.x + fmaxf(f.y, 0.f) * wf.y
                      + fmaxf(f.z, 0.f) * wf.z + fmaxf(f.w, 0.f) * wf.w
                      + fmaxf(hb4.x, 0.f) * wb.x + fmaxf(hb4.y, 0.f) * wb.y
                      + fmaxf(hb4.z, 0.f) * wb.z + fmaxf(hb4.w, 0.f) * wb.w;
            }
#pragma unroll
            for (int off = 16; off; off >>= 1)
                facc += __shfl_xor_sync(0xffffffffu, facc, off);
            if (ln == 0) out[(size_t)b * T + t] = facc + b_fc1[0];
        }

        nbar++; grid_sync(nbar * NBLK);
    }
}

// ---------------------------------------------------------------------------
extern "C" void kernel_launch(void* const* d_in, const int* in_sizes, int n_in,
                              void* d_out, int out_size) {
    const float* dec   = (const float*)d_in[0];
    // d_in[1] = lengths (T derives from out_size)
    const float* Wih_f = (const float*)d_in[2];
    const float* Whh_f = (const float*)d_in[3];
    const float* b_f   = (const float*)d_in[4];
    const float* Wih_b = (const float*)d_in[5];
    const float* Whh_b = (const float*)d_in[6];
    const float* b_b   = (const float*)d_in[7];
    const float* W_out = (const float*)d_in[8];
    const float* b_out = (const float*)d_in[9];
    const float* W_fc1 = (const float*)d_in[10];
    const float* b_fc1 = (const float*)d_in[11];
    float* out = (float*)d_out;

    const int T = out_size / BS;

    cudaFuncSetAttribute(lstm_persist, cudaFuncAttributeMaxDynamicSharedMemorySize, DYN_SMEM);

    prep_kernel<<<1024, 256>>>(Wih_f, Whh_f, b_f, Wih_b, Whh_b, b_b, dec);
    if (T > 0) {
        lstm_persist<<<NBLK, NTHR, DYN_SMEM>>>(T, out, W_out, b_out, W_fc1, b_fc1);
    }
}

// round 11
// speedup vs baseline: 1.4814x; 1.1078x over previous
#include <cuda_runtime.h>
#include <cuda_fp16.h>
#include <math.h>
#include <stdint.h>

#define BS 128
#define LATENT 512
#define HID 1024
#define G4 4096       // 4*HID
#define KTOT 1536     // LATENT + HID unified K
#define NBLK 128
#define NTHR 256
#define NCHUNK 24     // KTOT / 64
#define CHK 64        // fp16 K elems per chunk (= 128 bytes/row)

typedef unsigned long long u64;
typedef unsigned int u32;

// ---------------- persistent device-global state (no runtime alloc) --------
__device__ __align__(16) __half g_W[2][G4][KTOT];       // weight, fp16, gate-interleaved
__device__ __align__(16) __half g_Ahi[2][2][BS][KTOT];  // [buf][dir][row][k] activation hi
__device__ __align__(16) __half g_Alo[2][2][BS][KTOT];  // activation lo (fp32 residual)
__device__ __align__(16) float g_bias[2][G4];           // gate-interleaved bias
__device__ __align__(16) float g_h[2][2][BS][HID];      // fp32 h for head [buf][dir]
__device__ __align__(16) float g_c[2][BS][HID];         // cell state [dir]
__device__ u64 g_arrive;                                // grid barrier counter

// ---------------- helpers --------------------------------------------------
__device__ __forceinline__ void unpack2(u64 v, float& lo, float& hi) {
    asm("mov.b64 {%0, %1}, %2;" : "=f"(lo), "=f"(hi) : "l"(v));
}
__device__ __forceinline__ void fma2(u64& d, u64 a, u64 b) {
    asm("fma.rn.f32x2 %0, %1, %2, %0;" : "+l"(d) : "l"(a), "l"(b));
}
__device__ __forceinline__ u32 smem_u32(const void* p) {
    u32 a; asm("{ .reg .u64 t; cvta.to.shared.u64 t, %1; cvt.u32.u64 %0, t; }" : "=r"(a) : "l"(p));
    return a;
}

#define SW128(x) ((x) ^ (((x) >> 3) & 0x70))

#define CP16(dst, src) \
    asm volatile("cp.async.cg.shared.global [%0], [%1], 16;" :: "r"(dst), "l"(src))
#define CP_COMMIT() asm volatile("cp.async.commit_group;" ::: "memory")
#define CP_WAIT(n)  asm volatile("cp.async.wait_group %0;" :: "n"(n) : "memory")

#define LDSM4(R, A)                                                          \
    asm volatile("ldmatrix.sync.aligned.m8n8.x4.shared.b16 {%0,%1,%2,%3}, [%4];" \
                 : "=r"((R)[0]), "=r"((R)[1]), "=r"((R)[2]), "=r"((R)[3])    \
                 : "r"(A))

#define MMA16816(D, A, B0, B1)                                               \
    asm volatile("mma.sync.aligned.m16n8k16.row.col.f32.f16.f16.f32 "        \
                 "{%0,%1,%2,%3}, {%4,%5,%6,%7}, {%8,%9}, {%0,%1,%2,%3};"     \
                 : "+f"((D)[0]), "+f"((D)[1]), "+f"((D)[2]), "+f"((D)[3])    \
                 : "r"((A)[0]), "r"((A)[1]), "r"((A)[2]), "r"((A)[3]),       \
                   "r"(B0), "r"(B1))

// Fence-free grid barrier. Release via atom.add.release.gpu; acquire via
// leader ld.acquire.gpu poll. No CCTL.IVALL: all cross-block reads bypass
// L1 (cp.async.cg / __ldcg); block-private (g_c) and read-only data stays
// L1-resident across steps.
__device__ __forceinline__ void grid_sync(u64 target) {
    __syncthreads();
    if (threadIdx.x == 0) {
        u64 old;
        asm volatile("atom.add.release.gpu.u64 %0, [%1], 1;"
                     : "=l"(old) : "l"(&g_arrive) : "memory");
        u64 v;
        do {
            asm volatile("ld.acquire.gpu.u64 %0, [%1];"
                         : "=l"(v) : "l"(&g_arrive) : "memory");
        } while (v < target);
    }
    __syncthreads();
}

// fast nonlinearities (MUFU-based; rel err ~1e-6)
__device__ __forceinline__ float fast_sigmoid(float x) {
    return __fdividef(1.f, 1.f + __expf(-x));
}
__device__ __forceinline__ float fast_tanh(float x) {
    return 1.f - __fdividef(2.f, 1.f + __expf(2.f * x));
}

// smem: 3 stages of 40 KB. Stage layout: Ah 16K | Al 16K | W 8K
#define STG    40960
#define OFF_AL 16384
#define OFF_W  32768
#define DYN_SMEM (3 * STG)

// ---------------------------------------------------------------------------
// prep: gate-interleave weights (fp16) into unified-K layout; split
// activations to fp16 hi/lo; init h, c, barrier.
// reordered row r -> orig row (r&3)*HID + (r>>2); K: [0,512)=Wih, [512,1536)=Whh
// ---------------------------------------------------------------------------
__global__ void prep_kernel(const float* __restrict__ Wih_f, const float* __restrict__ Whh_f,
                            const float* __restrict__ b_f,
                            const float* __restrict__ Wih_b, const float* __restrict__ Whh_b,
                            const float* __restrict__ b_b,
                            const float* __restrict__ dec) {
    int idx = blockIdx.x * blockDim.x + threadIdx.x;
    int stride = gridDim.x * blockDim.x;
    if (idx == 0) g_arrive = 0ULL;

    for (int i = idx; i < 2 * G4 * KTOT; i += stride) {
        int dir = i / (G4 * KTOT);
        int rem = i - dir * (G4 * KTOT);
        int r = rem / KTOT, k = rem - r * KTOT;
        int orow = (r & 3) * HID + (r >> 2);
        float w;
        if (k < LATENT) w = (dir ? Wih_b : Wih_f)[orow * LATENT + k];
        else            w = (dir ? Whh_b : Whh_f)[orow * HID + (k - LATENT)];
        g_W[dir][r][k] = __float2half_rn(w);
    }
    for (int i = idx; i < 2 * G4; i += stride) {
        int dir = i / G4, r = i - dir * G4;
        g_bias[dir][r] = (dir ? b_b : b_f)[(r & 3) * HID + (r >> 2)];
    }
    for (int i = idx; i < 2 * 2 * BS * KTOT; i += stride) {
        int buf = i / (2 * BS * KTOT);
        int rem = i - buf * (2 * BS * KTOT);
        int dir = rem / (BS * KTOT);
        int rem2 = rem - dir * (BS * KTOT);
        int row = rem2 / KTOT, k = rem2 - row * KTOT;
        float v = (buf == 0 && k < LATENT) ? dec[row * LATENT + k] : 0.f;
        __half hi = __float2half_rn(v);
        __half lo = __float2half_rn(v - __half2float(hi));
        g_Ahi[buf][dir][row][k] = hi;
        g_Alo[buf][dir][row][k] = lo;
    }
    for (int i = idx; i < 2 * 2 * BS * HID; i += stride) ((float*)g_h)[i] = 0.f;
    for (int i = idx; i < 2 * BS * HID; i += stride)     ((float*)g_c)[i] = 0.f;
}

// ---------------------------------------------------------------------------
// persistent kernel: 128 blocks x 256 threads, one launch for all T steps.
// phase A: block = (dir, 64 gate-cols); 4x2 warp grid, warp tile 32(M)x32(N).
//          fp16 2-term split mma.sync (z = Ah*W + Al*W); cp.async 3-stage ring.
// phase B: head (x_next GEMM + fc1), FFMA2.
// ---------------------------------------------------------------------------
__global__ void __launch_bounds__(NTHR, 1) lstm_persist(
        int T, float* __restrict__ out,
        const float* __restrict__ W_out, const float* __restrict__ b_out,
        const float* __restrict__ W_fc1, const float* __restrict__ b_fc1) {

    extern __shared__ __align__(16) unsigned char dsm[];
    const u32 smem_base = smem_u32(dsm);

    const int tid = threadIdx.x;
    const int bid = blockIdx.x;
    const int wid = tid >> 5;
    const int lane = tid & 31;

    const int dir = bid >> 6;
    const int colbase = (bid & 63) << 6;

    // warp tile mapping: 4 warps along M (32 rows), 2 along N (32 cols)
    const int wm = wid & 3;
    const int wn = wid >> 2;
    const int R0 = wm * 32;
    const int C0 = wn * 32;

    // ldmatrix per-lane constants
    const int arow = lane & 15;                          // A: m16 row within tile
    const u32 khA = (u32)(lane >> 4) * 16;               // A: k-half byte offset
    const int brow = (lane & 7) + ((lane >> 4) & 1) * 8; // B: n row within n16 pair
    const u32 khB = (u32)((lane >> 3) & 1) * 16;         // B: k-half byte offset
    const u32 swA = (u32)(arow & 7) << 4;
    const u32 swB = (u32)(brow & 7) << 4;
    // stage-relative byte offsets of the ldmatrix base rows
    const u32 aRowOff0 = (u32)(R0 + arow) * 128;
    const u32 aRowOff1 = (u32)(R0 + 16 + arow) * 128;
    const u32 bRowOff0 = OFF_W + (u32)(C0 + brow) * 128;
    const u32 bRowOff1 = OFF_W + (u32)(C0 + 16 + brow) * 128;

    // cp.async per-thread source/dest precompute
    u32 cpdstA[4], cpdstW[2];
    int cprowA[4], cpqA[4], cprowW[2], cpqW[2];
#pragma unroll
    for (int i = 0; i < 4; i++) {
        int p = tid + i * NTHR, row = p >> 3, q = p & 7;
        cprowA[i] = row; cpqA[i] = q;
        cpdstA[i] = SW128((u32)(row * 128 + q * 16));
    }
#pragma unroll
    for (int i = 0; i < 2; i++) {
        int p = tid + i * NTHR, row = p >> 3, q = p & 7;
        cprowW[i] = row; cpqW[i] = q;
        cpdstW[i] = SW128((u32)(row * 128 + q * 16));
    }

    // head mapping
    const int bt = bid >> 3;   // 16 row-tiles of 8
    const int lt = bid & 7;    // 8 latent col-tiles of 64
    float (*s_hb)[HID] = (float (*)[HID])dsm;

    u64 nbar = 0;

    for (int t = 0; t < T; t++) {
        const int cur = t & 1;
        const int nxt = cur ^ 1;
        const __half* __restrict__ Ah = &g_Ahi[cur][dir][0][0];
        const __half* __restrict__ Al = &g_Alo[cur][dir][0][0];
        const __half* __restrict__ Wp = &g_W[dir][colbase][0];

#define ISSUE_CHUNK(cc, st)                                                   \
        {                                                                      \
            const u32 sb = smem_base + (u32)(st) * STG;                        \
            const size_t c64 = (size_t)(cc) * CHK;                             \
            _Pragma("unroll")                                                  \
            for (int i = 0; i < 4; i++) {                                      \
                const char* s  = (const char*)(Ah + (size_t)cprowA[i] * KTOT + c64) + cpqA[i] * 16; \
                const char* s2 = (const char*)(Al + (size_t)cprowA[i] * KTOT + c64) + cpqA[i] * 16; \
                CP16(sb + cpdstA[i], s);                                       \
                CP16(sb + OFF_AL + cpdstA[i], s2);                             \
            }                                                                  \
            _Pragma("unroll")                                                  \
            for (int i = 0; i < 2; i++) {                                      \
                const char* s = (const char*)(Wp + (size_t)cprowW[i] * KTOT + c64) + cpqW[i] * 16; \
                CP16(sb + OFF_W + cpdstW[i], s);                               \
            }                                                                  \
            CP_COMMIT();                                                       \
        }

        // ================= phase A: fp16 2-term HMMA pipeline ==============
        float acc[2][4][4];
#pragma unroll
        for (int mt = 0; mt < 2; mt++)
#pragma unroll
            for (int nt = 0; nt < 4; nt++)
#pragma unroll
                for (int i = 0; i < 4; i++) acc[mt][nt][i] = 0.f;

        ISSUE_CHUNK(0, 0);

        int stage = 0;
#pragma unroll 1
        for (int c = 0; c < NCHUNK; c++) {
            if (c + 1 < NCHUNK) {
                const int nstage = (stage == 2) ? 0 : stage + 1;
                ISSUE_CHUNK(c + 1, nstage);
                CP_WAIT(1);          // chunk c complete (c+1 may be in flight)
            } else {
                CP_WAIT(0);
            }
            __syncthreads();         // chunk c visible; ring period 3 protects reuse

            const u32 sb = smem_base + (u32)stage * STG;
            const u32 a0 = sb + aRowOff0, a1 = sb + aRowOff1;
            const u32 b0 = sb + bRowOff0, b1 = sb + bRowOff1;

#pragma unroll
            for (int kk = 0; kk < 4; kk++) {
                const u32 xA = ((u32)(kk * 32) + khA) ^ swA;
                const u32 xB = ((u32)(kk * 32) + khB) ^ swB;
                u32 ah[2][4], al[2][4], bw[2][4];
                LDSM4(ah[0], a0 + xA);
                LDSM4(ah[1], a1 + xA);
                LDSM4(al[0], a0 + OFF_AL + xA);
                LDSM4(al[1], a1 + OFF_AL + xA);
                LDSM4(bw[0], b0 + xB);
                LDSM4(bw[1], b1 + xB);
#pragma unroll
                for (int mt = 0; mt < 2; mt++)
#pragma unroll
                    for (int np = 0; np < 2; np++)
#pragma unroll
                        for (int hf = 0; hf < 2; hf++) {
                            const int nt = np * 2 + hf;
                            MMA16816(acc[mt][nt], ah[mt], bw[np][2 * hf], bw[np][2 * hf + 1]);
                            MMA16816(acc[mt][nt], al[mt], bw[np][2 * hf], bw[np][2 * hf + 1]);
                        }
            }
            stage = (stage == 2) ? 0 : stage + 1;
        }

        // -------- epilogue: pair-exchange quads, LSTM cell, write h --------
#pragma unroll
        for (int mt = 0; mt < 2; mt++)
#pragma unroll
            for (int nt = 0; nt < 4; nt++) {
                float d0 = acc[mt][nt][0], d1 = acc[mt][nt][1];
                float d2 = acc[mt][nt][2], d3 = acc[mt][nt][3];
                float p0 = __shfl_xor_sync(0xffffffffu, d0, 1);
                float p1 = __shfl_xor_sync(0xffffffffu, d1, 1);
                float p2 = __shfl_xor_sync(0xffffffffu, d2, 1);
                float p3 = __shfl_xor_sync(0xffffffffu, d3, 1);
                if (!(lane & 1)) {
                    const int q = (lane >> 1) & 1;
                    const int col4 = colbase + C0 + nt * 8 + q * 4;
                    const int jp = col4 >> 2;
                    const float4 b4 = *(const float4*)&g_bias[dir][col4];
                    const int r0 = R0 + mt * 16 + (lane >> 2);
#pragma unroll
                    for (int rr = 0; rr < 2; rr++) {
                        const int row = r0 + rr * 8;
                        float zi = (rr ? d2 : d0) + b4.x;
                        float zf = (rr ? d3 : d1) + b4.y;
                        float zg = (rr ? p2 : p0) + b4.z;
                        float zo = (rr ? p3 : p1) + b4.w;
                        float si = fast_sigmoid(zi);
                        float sf = fast_sigmoid(zf);
                        float so = fast_sigmoid(zo);
                        float c2 = sf * g_c[dir][row][jp] + si * fast_tanh(zg);
                        g_c[dir][row][jp] = c2;
                        float hv = so * fast_tanh(c2);
                        g_h[nxt][dir][row][jp] = hv;
                        __half hhi = __float2half_rn(hv);
                        __half hlo = __float2half_rn(hv - __half2float(hhi));
                        g_Ahi[nxt][dir][row][LATENT + jp] = hhi;
                        g_Alo[nxt][dir][row][LATENT + jp] = hlo;
                    }
                }
            }

        nbar++; grid_sync(nbar * NBLK);

        // ================= phase B: head ===================================
        // stage hb rows bt*8..+7 into smem (L2-direct: written by other blocks)
        for (int i = tid; i < 8 * HID / 4; i += NTHR) {
            int r = i >> 8;               // 256 float4 per row
            int k = (i & 255) * 4;
            *(float4*)&s_hb[r][k] = __ldcg((const float4*)&g_h[nxt][1][bt * 8 + r][k]);
        }
        __syncthreads();

        // x_next = hb @ W_out^T + b_out, split to fp16 hi/lo for both dirs
        {
            const int l_loc = tid >> 2;
            const int q = tid & 3;
            const int l = lt * 64 + l_loc;
            const u64* __restrict__ wp = (const u64*)(W_out + (size_t)l * HID + q * 256);
            const u64* __restrict__ hp = (const u64*)&s_hb[0][q * 256];
            u64 hacc[8];
#pragma unroll
            for (int r = 0; r < 8; r++) hacc[r] = 0ull;
#pragma unroll 2
            for (int k2 = 0; k2 < 128; k2++) {
                u64 w = wp[k2];
#pragma unroll
                for (int r = 0; r < 8; r++) fma2(hacc[r], w, hp[r * 512 + k2]);
            }
#pragma unroll
            for (int r = 0; r < 8; r++) {
                float lo, hi; unpack2(hacc[r], lo, hi);
                float s = lo + hi;
                s += __shfl_xor_sync(0xffffffffu, s, 1);
                s += __shfl_xor_sync(0xffffffffu, s, 2);
                if (q == 0) {
                    float xv = s + b_out[l];
                    int row = bt * 8 + r;
                    __half xh = __float2half_rn(xv);
                    __half xl = __float2half_rn(xv - __half2float(xh));
                    g_Ahi[nxt][0][row][l] = xh;
                    g_Ahi[nxt][1][row][l] = xh;
                    g_Alo[nxt][0][row][l] = xl;
                    g_Alo[nxt][1][row][l] = xl;
                }
            }
        }

        // out[b, t] = relu(concat(hf,hb)) . W_fc1 + b_fc1   (lt==0 blocks)
        if (lt == 0) {
            const int r = tid >> 5, ln = tid & 31;
            const int b = bt * 8 + r;
            const float* __restrict__ hf = &g_h[nxt][0][b][0];
            float facc = 0.f;
            for (int k = ln * 4; k < HID; k += 128) {
                float4 f   = __ldcg((const float4*)&hf[k]);
                float4 wf  = *(const float4*)&W_fc1[k];
                float4 hb4 = *(const float4*)&s_hb[r][k];
                float4 wb  = *(const float4*)&W_fc1[HID + k];
                facc += fmaxf(f.x, 0.f) * wf.x + fmaxf(f.y, 0.f) * wf.y
                      + fmaxf(f.z, 0.f) * wf.z + fmaxf(f.w, 0.f) * wf.w
                      + fmaxf(hb4.x, 0.f) * wb.x + fmaxf(hb4.y, 0.f) * wb.y
                      + fmaxf(hb4.z, 0.f) * wb.z + fmaxf(hb4.w, 0.f) * wb.w;
            }
#pragma unroll
            for (int off = 16; off; off >>= 1)
                facc += __shfl_xor_sync(0xffffffffu, facc, off);
            if (ln == 0) out[(size_t)b * T + t] = facc + b_fc1[0];
        }

        nbar++; grid_sync(nbar * NBLK);
    }
}

// ---------------------------------------------------------------------------
extern "C" void kernel_launch(void* const* d_in, const int* in_sizes, int n_in,
                              void* d_out, int out_size) {
    const float* dec   = (const float*)d_in[0];
    // d_in[1] = lengths (T derives from out_size)
    const float* Wih_f = (const float*)d_in[2];
    const float* Whh_f = (const float*)d_in[3];
    const float* b_f   = (const float*)d_in[4];
    const float* Wih_b = (const float*)d_in[5];
    const float* Whh_b = (const float*)d_in[6];
    const float* b_b   = (const float*)d_in[7];
    const float* W_out = (const float*)d_in[8];
    const float* b_out = (const float*)d_in[9];
    const float* W_fc1 = (const float*)d_in[10];
    const float* b_fc1 = (const float*)d_in[11];
    float* out = (float*)d_out;

    const int T = out_size / BS;

    cudaFuncSetAttribute(lstm_persist, cudaFuncAttributeMaxDynamicSharedMemorySize, DYN_SMEM);

    prep_kernel<<<1024, 256>>>(Wih_f, Whh_f, b_f, Wih_b, Whh_b, b_b, dec);
    if (T > 0) {
        lstm_persist<<<NBLK, NTHR, DYN_SMEM>>>(T, out, W_out, b_out, W_fc1, b_fc1);
    }
}

// round 12
// speedup vs baseline: 1.6098x; 1.0867x over previous
#include <cuda_runtime.h>
#include <cuda_fp16.h>
#include <math.h>
#include <stdint.h>

#define BS 128
#define LATENT 512
#define HID 1024
#define G4 4096       // 4*HID
#define KTOT 1536     // LATENT + HID unified K
#define NBLK 128
#define NTHR 256
#define NCHUNK 24     // KTOT / 64
#define CHK 64        // fp16 K elems per chunk (= 128 bytes/row)

// phase-B padded s_hb layout: 4 segments of 260 floats per row (256 used)
#define SEGF 260
#define ROWF (4 * SEGF)   // 1040 floats per row

typedef unsigned long long u64;
typedef unsigned int u32;

// ---------------- persistent device-global state (no runtime alloc) --------
__device__ __align__(16) __half g_W[2][G4][KTOT];       // weight, fp16, gate-interleaved
__device__ __align__(16) __half g_Ahi[2][2][BS][KTOT];  // [buf][dir][row][k] activation hi
__device__ __align__(16) __half g_Alo[2][2][BS][KTOT];  // activation lo (fp32 residual)
__device__ __align__(16) float g_bias[2][G4];           // gate-interleaved bias
__device__ __align__(16) float g_h[2][2][BS][HID];      // fp32 h for head [buf][dir]
__device__ __align__(16) float g_c[2][BS][HID];         // cell state [dir]
__device__ u64 g_arrive;                                // grid barrier counter

// ---------------- helpers --------------------------------------------------
__device__ __forceinline__ void unpack2(u64 v, float& lo, float& hi) {
    asm("mov.b64 {%0, %1}, %2;" : "=f"(lo), "=f"(hi) : "l"(v));
}
__device__ __forceinline__ void fma2(u64& d, u64 a, u64 b) {
    asm("fma.rn.f32x2 %0, %1, %2, %0;" : "+l"(d) : "l"(a), "l"(b));
}
__device__ __forceinline__ u32 smem_u32(const void* p) {
    u32 a; asm("{ .reg .u64 t; cvta.to.shared.u64 t, %1; cvt.u32.u64 %0, t; }" : "=r"(a) : "l"(p));
    return a;
}

#define SW128(x) ((x) ^ (((x) >> 3) & 0x70))

#define CP16(dst, src) \
    asm volatile("cp.async.cg.shared.global [%0], [%1], 16;" :: "r"(dst), "l"(src))
#define CP_COMMIT() asm volatile("cp.async.commit_group;" ::: "memory")
#define CP_WAIT(n)  asm volatile("cp.async.wait_group %0;" :: "n"(n) : "memory")

#define LDSM4(R, A)                                                          \
    asm volatile("ldmatrix.sync.aligned.m8n8.x4.shared.b16 {%0,%1,%2,%3}, [%4];" \
                 : "=r"((R)[0]), "=r"((R)[1]), "=r"((R)[2]), "=r"((R)[3])    \
                 : "r"(A))

#define MMA16816(D, A, B0, B1)                                               \
    asm volatile("mma.sync.aligned.m16n8k16.row.col.f32.f16.f16.f32 "        \
                 "{%0,%1,%2,%3}, {%4,%5,%6,%7}, {%8,%9}, {%0,%1,%2,%3};"     \
                 : "+f"((D)[0]), "+f"((D)[1]), "+f"((D)[2]), "+f"((D)[3])    \
                 : "r"((A)[0]), "r"((A)[1]), "r"((A)[2]), "r"((A)[3]),       \
                   "r"(B0), "r"(B1))

// Fence-free grid barrier. Release via atom.add.release.gpu; acquire via
// leader ld.acquire.gpu poll. No CCTL.IVALL: all cross-block reads bypass
// L1 (cp.async.cg / __ldcg); block-private (g_c) and read-only data stays
// L1-resident across steps.
__device__ __forceinline__ void grid_sync(u64 target) {
    __syncthreads();
    if (threadIdx.x == 0) {
        u64 old;
        asm volatile("atom.add.release.gpu.u64 %0, [%1], 1;"
                     : "=l"(old) : "l"(&g_arrive) : "memory");
        u64 v;
        do {
            asm volatile("ld.acquire.gpu.u64 %0, [%1];"
                         : "=l"(v) : "l"(&g_arrive) : "memory");
        } while (v < target);
    }
    __syncthreads();
}

// fast nonlinearities (MUFU-based; rel err ~1e-6)
__device__ __forceinline__ float fast_sigmoid(float x) {
    return __fdividef(1.f, 1.f + __expf(-x));
}
__device__ __forceinline__ float fast_tanh(float x) {
    return 1.f - __fdividef(2.f, 1.f + __expf(2.f * x));
}

// smem: 3 stages of 40 KB. Stage layout: Ah 16K | Al 16K | W 8K
#define STG    40960
#define OFF_AL 16384
#define OFF_W  32768
#define DYN_SMEM (3 * STG)

// ---------------------------------------------------------------------------
// prep: gate-interleave weights (fp16) into unified-K layout; split
// activations to fp16 hi/lo; init h, c, barrier.
// reordered row r -> orig row (r&3)*HID + (r>>2); K: [0,512)=Wih, [512,1536)=Whh
// ---------------------------------------------------------------------------
__global__ void prep_kernel(const float* __restrict__ Wih_f, const float* __restrict__ Whh_f,
                            const float* __restrict__ b_f,
                            const float* __restrict__ Wih_b, const float* __restrict__ Whh_b,
                            const float* __restrict__ b_b,
                            const float* __restrict__ dec) {
    int idx = blockIdx.x * blockDim.x + threadIdx.x;
    int stride = gridDim.x * blockDim.x;
    if (idx == 0) g_arrive = 0ULL;

    for (int i = idx; i < 2 * G4 * KTOT; i += stride) {
        int dir = i / (G4 * KTOT);
        int rem = i - dir * (G4 * KTOT);
        int r = rem / KTOT, k = rem - r * KTOT;
        int orow = (r & 3) * HID + (r >> 2);
        float w;
        if (k < LATENT) w = (dir ? Wih_b : Wih_f)[orow * LATENT + k];
        else            w = (dir ? Whh_b : Whh_f)[orow * HID + (k - LATENT)];
        g_W[dir][r][k] = __float2half_rn(w);
    }
    for (int i = idx; i < 2 * G4; i += stride) {
        int dir = i / G4, r = i - dir * G4;
        g_bias[dir][r] = (dir ? b_b : b_f)[(r & 3) * HID + (r >> 2)];
    }
    for (int i = idx; i < 2 * 2 * BS * KTOT; i += stride) {
        int buf = i / (2 * BS * KTOT);
        int rem = i - buf * (2 * BS * KTOT);
        int dir = rem / (BS * KTOT);
        int rem2 = rem - dir * (BS * KTOT);
        int row = rem2 / KTOT, k = rem2 - row * KTOT;
        float v = (buf == 0 && k < LATENT) ? dec[row * LATENT + k] : 0.f;
        __half hi = __float2half_rn(v);
        __half lo = __float2half_rn(v - __half2float(hi));
        g_Ahi[buf][dir][row][k] = hi;
        g_Alo[buf][dir][row][k] = lo;
    }
    for (int i = idx; i < 2 * 2 * BS * HID; i += stride) ((float*)g_h)[i] = 0.f;
    for (int i = idx; i < 2 * BS * HID; i += stride)     ((float*)g_c)[i] = 0.f;
}

// ---------------------------------------------------------------------------
// persistent kernel: 128 blocks x 256 threads, one launch for all T steps.
// phase A: block = (dir, 64 gate-cols); 4x2 warp grid, warp tile 32(M)x32(N).
//          fp16 2-term split mma.sync (z = Ah*W + Al*W); cp.async 3-stage ring.
// phase B: head (x_next GEMM + fc1), FFMA2, bank-conflict-free segmented smem.
// ---------------------------------------------------------------------------
__global__ void __launch_bounds__(NTHR, 1) lstm_persist(
        int T, float* __restrict__ out,
        const float* __restrict__ W_out, const float* __restrict__ b_out,
        const float* __restrict__ W_fc1, const float* __restrict__ b_fc1) {

    extern __shared__ __align__(16) unsigned char dsm[];
    const u32 smem_base = smem_u32(dsm);

    const int tid = threadIdx.x;
    const int bid = blockIdx.x;
    const int wid = tid >> 5;
    const int lane = tid & 31;

    const int dir = bid >> 6;
    const int colbase = (bid & 63) << 6;

    // warp tile mapping: 4 warps along M (32 rows), 2 along N (32 cols)
    const int wm = wid & 3;
    const int wn = wid >> 2;
    const int R0 = wm * 32;
    const int C0 = wn * 32;

    // ldmatrix per-lane constants
    const int arow = lane & 15;                          // A: m16 row within tile
    const u32 khA = (u32)(lane >> 4) * 16;               // A: k-half byte offset
    const int brow = (lane & 7) + ((lane >> 4) & 1) * 8; // B: n row within n16 pair
    const u32 khB = (u32)((lane >> 3) & 1) * 16;         // B: k-half byte offset
    const u32 swA = (u32)(arow & 7) << 4;
    const u32 swB = (u32)(brow & 7) << 4;
    // stage-relative byte offsets of the ldmatrix base rows
    const u32 aRowOff0 = (u32)(R0 + arow) * 128;
    const u32 aRowOff1 = (u32)(R0 + 16 + arow) * 128;
    const u32 bRowOff0 = OFF_W + (u32)(C0 + brow) * 128;
    const u32 bRowOff1 = OFF_W + (u32)(C0 + 16 + brow) * 128;

    // cp.async per-thread source/dest precompute
    u32 cpdstA[4], cpdstW[2];
    int cprowA[4], cpqA[4], cprowW[2], cpqW[2];
#pragma unroll
    for (int i = 0; i < 4; i++) {
        int p = tid + i * NTHR, row = p >> 3, q = p & 7;
        cprowA[i] = row; cpqA[i] = q;
        cpdstA[i] = SW128((u32)(row * 128 + q * 16));
    }
#pragma unroll
    for (int i = 0; i < 2; i++) {
        int p = tid + i * NTHR, row = p >> 3, q = p & 7;
        cprowW[i] = row; cpqW[i] = q;
        cpdstW[i] = SW128((u32)(row * 128 + q * 16));
    }

    // head mapping
    const int bt = bid >> 3;   // 16 row-tiles of 8
    const int lt = bid & 7;    // 8 latent col-tiles of 64
    float* s_hb_f = (float*)dsm;   // segmented layout: r*ROWF + seg*SEGF + within

    u64 nbar = 0;

    for (int t = 0; t < T; t++) {
        const int cur = t & 1;
        const int nxt = cur ^ 1;
        const __half* __restrict__ Ah = &g_Ahi[cur][dir][0][0];
        const __half* __restrict__ Al = &g_Alo[cur][dir][0][0];
        const __half* __restrict__ Wp = &g_W[dir][colbase][0];

#define ISSUE_CHUNK(cc, st)                                                   \
        {                                                                      \
            const u32 sb = smem_base + (u32)(st) * STG;                        \
            const size_t c64 = (size_t)(cc) * CHK;                             \
            _Pragma("unroll")                                                  \
            for (int i = 0; i < 4; i++) {                                      \
                const char* s  = (const char*)(Ah + (size_t)cprowA[i] * KTOT + c64) + cpqA[i] * 16; \
                const char* s2 = (const char*)(Al + (size_t)cprowA[i] * KTOT + c64) + cpqA[i] * 16; \
                CP16(sb + cpdstA[i], s);                                       \
                CP16(sb + OFF_AL + cpdstA[i], s2);                             \
            }                                                                  \
            _Pragma("unroll")                                                  \
            for (int i = 0; i < 2; i++) {                                      \
                const char* s = (const char*)(Wp + (size_t)cprowW[i] * KTOT + c64) + cpqW[i] * 16; \
                CP16(sb + OFF_W + cpdstW[i], s);                               \
            }                                                                  \
            CP_COMMIT();                                                       \
        }

        // ================= phase A: fp16 2-term HMMA pipeline ==============
        float acc[2][4][4];
#pragma unroll
        for (int mt = 0; mt < 2; mt++)
#pragma unroll
            for (int nt = 0; nt < 4; nt++)
#pragma unroll
                for (int i = 0; i < 4; i++) acc[mt][nt][i] = 0.f;

        ISSUE_CHUNK(0, 0);

        int stage = 0;
#pragma unroll 1
        for (int c = 0; c < NCHUNK; c++) {
            if (c + 1 < NCHUNK) {
                const int nstage = (stage == 2) ? 0 : stage + 1;
                ISSUE_CHUNK(c + 1, nstage);
                CP_WAIT(1);          // chunk c complete (c+1 may be in flight)
            } else {
                CP_WAIT(0);
            }
            __syncthreads();         // chunk c visible; ring period 3 protects reuse

            const u32 sb = smem_base + (u32)stage * STG;
            const u32 a0 = sb + aRowOff0, a1 = sb + aRowOff1;
            const u32 b0 = sb + bRowOff0, b1 = sb + bRowOff1;

#pragma unroll
            for (int kk = 0; kk < 4; kk++) {
                const u32 xA = ((u32)(kk * 32) + khA) ^ swA;
                const u32 xB = ((u32)(kk * 32) + khB) ^ swB;
                u32 ah[2][4], al[2][4], bw[2][4];
                LDSM4(ah[0], a0 + xA);
                LDSM4(ah[1], a1 + xA);
                LDSM4(al[0], a0 + OFF_AL + xA);
                LDSM4(al[1], a1 + OFF_AL + xA);
                LDSM4(bw[0], b0 + xB);
                LDSM4(bw[1], b1 + xB);
#pragma unroll
                for (int mt = 0; mt < 2; mt++)
#pragma unroll
                    for (int np = 0; np < 2; np++)
#pragma unroll
                        for (int hf = 0; hf < 2; hf++) {
                            const int nt = np * 2 + hf;
                            MMA16816(acc[mt][nt], ah[mt], bw[np][2 * hf], bw[np][2 * hf + 1]);
                            MMA16816(acc[mt][nt], al[mt], bw[np][2 * hf], bw[np][2 * hf + 1]);
                        }
            }
            stage = (stage == 2) ? 0 : stage + 1;
        }

        // -------- epilogue: pair-exchange quads, LSTM cell, write h --------
#pragma unroll
        for (int mt = 0; mt < 2; mt++)
#pragma unroll
            for (int nt = 0; nt < 4; nt++) {
                float d0 = acc[mt][nt][0], d1 = acc[mt][nt][1];
                float d2 = acc[mt][nt][2], d3 = acc[mt][nt][3];
                float p0 = __shfl_xor_sync(0xffffffffu, d0, 1);
                float p1 = __shfl_xor_sync(0xffffffffu, d1, 1);
                float p2 = __shfl_xor_sync(0xffffffffu, d2, 1);
                float p3 = __shfl_xor_sync(0xffffffffu, d3, 1);
                if (!(lane & 1)) {
                    const int q = (lane >> 1) & 1;
                    const int col4 = colbase + C0 + nt * 8 + q * 4;
                    const int jp = col4 >> 2;
                    const float4 b4 = *(const float4*)&g_bias[dir][col4];
                    const int r0 = R0 + mt * 16 + (lane >> 2);
#pragma unroll
                    for (int rr = 0; rr < 2; rr++) {
                        const int row = r0 + rr * 8;
                        float zi = (rr ? d2 : d0) + b4.x;
                        float zf = (rr ? d3 : d1) + b4.y;
                        float zg = (rr ? p2 : p0) + b4.z;
                        float zo = (rr ? p3 : p1) + b4.w;
                        float si = fast_sigmoid(zi);
                        float sf = fast_sigmoid(zf);
                        float so = fast_sigmoid(zo);
                        float c2 = sf * g_c[dir][row][jp] + si * fast_tanh(zg);
                        g_c[dir][row][jp] = c2;
                        float hv = so * fast_tanh(c2);
                        g_h[nxt][dir][row][jp] = hv;
                        __half hhi = __float2half_rn(hv);
                        __half hlo = __float2half_rn(hv - __half2float(hhi));
                        g_Ahi[nxt][dir][row][LATENT + jp] = hhi;
                        g_Alo[nxt][dir][row][LATENT + jp] = hlo;
                    }
                }
            }

        nbar++; grid_sync(nbar * NBLK);

        // ================= phase B: head ===================================
        // stage hb rows bt*8..+7 into segmented smem (L2-direct source).
        // element k of row r -> offset r*ROWF + (k>>8)*SEGF + (k&255)
        for (int i = tid; i < 8 * 256; i += NTHR) {
            int r = i >> 8;               // 0..7
            int k = (i & 255) * 4;        // 0..1020
            float4 v = __ldcg((const float4*)&g_h[nxt][1][bt * 8 + r][k]);
            *(float4*)&s_hb_f[r * ROWF + (k >> 8) * SEGF + (k & 255)] = v;
        }
        __syncthreads();

        // x_next = hb @ W_out^T + b_out, split to fp16 hi/lo for both dirs.
        // q-segments start at banks {0,4,8,12}; 8 l-lanes broadcast -> no conflicts.
        {
            const int l_loc = tid >> 2;
            const int q = tid & 3;
            const int l = lt * 64 + l_loc;
            const ulonglong2* __restrict__ wp2 =
                (const ulonglong2*)(W_out + (size_t)l * HID) + q * 64;
            const u64* __restrict__ hp = (const u64*)dsm + q * (SEGF / 2);
            u64 hacc[8];
#pragma unroll
            for (int r = 0; r < 8; r++) hacc[r] = 0ull;
#pragma unroll 2
            for (int k4 = 0; k4 < 64; k4++) {
                ulonglong2 ww = wp2[k4];
#pragma unroll
                for (int r = 0; r < 8; r++) {
                    fma2(hacc[r], ww.x, hp[r * (ROWF / 2) + 2 * k4]);
                    fma2(hacc[r], ww.y, hp[r * (ROWF / 2) + 2 * k4 + 1]);
                }
            }
#pragma unroll
            for (int r = 0; r < 8; r++) {
                float lo, hi; unpack2(hacc[r], lo, hi);
                float s = lo + hi;
                s += __shfl_xor_sync(0xffffffffu, s, 1);
                s += __shfl_xor_sync(0xffffffffu, s, 2);
                if (q == 0) {
                    float xv = s + b_out[l];
                    int row = bt * 8 + r;
                    __half xh = __float2half_rn(xv);
                    __half xl = __float2half_rn(xv - __half2float(xh));
                    g_Ahi[nxt][0][row][l] = xh;
                    g_Ahi[nxt][1][row][l] = xh;
                    g_Alo[nxt][0][row][l] = xl;
                    g_Alo[nxt][1][row][l] = xl;
                }
            }
        }

        // out[b, t] = relu(concat(hf,hb)) . W_fc1 + b_fc1   (lt==0 blocks)
        if (lt == 0) {
            const int r = tid >> 5, ln = tid & 31;
            const int b = bt * 8 + r;
            const float* __restrict__ hf = &g_h[nxt][0][b][0];
            float facc = 0.f;
            for (int k = ln * 4; k < HID; k += 128) {
                float4 f   = __ldcg((const float4*)&hf[k]);
                float4 wf  = *(const float4*)&W_fc1[k];
                float4 hb4 = *(const float4*)&s_hb_f[r * ROWF + (k >> 8) * SEGF + (k & 255)];
                float4 wb  = *(const float4*)&W_fc1[HID + k];
                facc += fmaxf(f.x, 0.f) * wf.x + fmaxf(f.y, 0.f) * wf.y
                      + fmaxf(f.z, 0.f) * wf.z + fmaxf(f.w, 0.f) * wf.w
                      + fmaxf(hb4.x, 0.f) * wb.x + fmaxf(hb4.y, 0.f) * wb.y
                      + fmaxf(hb4.z, 0.f) * wb.z + fmaxf(hb4.w, 0.f) * wb.w;
            }
#pragma unroll
            for (int off = 16; off; off >>= 1)
                facc += __shfl_xor_sync(0xffffffffu, facc, off);
            if (ln == 0) out[(size_t)b * T + t] = facc + b_fc1[0];
        }

        nbar++; grid_sync(nbar * NBLK);
    }
}

// ---------------------------------------------------------------------------
extern "C" void kernel_launch(void* const* d_in, const int* in_sizes, int n_in,
                              void* d_out, int out_size) {
    const float* dec   = (const float*)d_in[0];
    // d_in[1] = lengths (T derives from out_size)
    const float* Wih_f = (const float*)d_in[2];
    const float* Whh_f = (const float*)d_in[3];
    const float* b_f   = (const float*)d_in[4];
    const float* Wih_b = (const float*)d_in[5];
    const float* Whh_b = (const float*)d_in[6];
    const float* b_b   = (const float*)d_in[7];
    const float* W_out = (const float*)d_in[8];
    const float* b_out = (const float*)d_in[9];
    const float* W_fc1 = (const float*)d_in[10];
    const float* b_fc1 = (const float*)d_in[11];
    float* out = (float*)d_out;

    const int T = out_size / BS;

    cudaFuncSetAttribute(lstm_persist, cudaFuncAttributeMaxDynamicSharedMemorySize, DYN_SMEM);

    prep_kernel<<<1024, 256>>>(Wih_f, Whh_f, b_f, Wih_b, Whh_b, b_b, dec);
    if (T > 0) {
        lstm_persist<<<NBLK, NTHR, DYN_SMEM>>>(T, out, W_out, b_out, W_fc1, b_fc1);
    }
}

// round 13
// speedup vs baseline: 2.4196x; 1.5031x over previous
#include <cuda_runtime.h>
#include <cuda_fp16.h>
#include <math.h>
#include <stdint.h>

#define BS 128
#define LATENT 512
#define HID 1024
#define G4 4096       // 4*HID
#define KTOT 1536     // LATENT + HID unified K
#define NBLK 128
#define NTHR 256
#define NCHUNK 24     // KTOT / 64
#define CHK 64        // fp16 K elems per chunk (= 128 bytes/row)

// iteration -> K-chunk map: h-part (chunks 8..23) first, x-part (0..7) last
#define MAPC(c) ((c) < 16 ? (c) + 8 : (c) - 16)

// phase-B padded s_hb layout: 4 segments of 260 floats per row (256 used)
#define SEGF 260
#define ROWF (4 * SEGF)   // 1040 floats per row

typedef unsigned long long u64;
typedef unsigned int u32;

// ---------------- persistent device-global state (no runtime alloc) --------
__device__ __align__(16) __half g_W[2][G4][KTOT];       // weight, fp16, gate-interleaved
__device__ __align__(16) __half g_Ahi[2][2][BS][KTOT];  // [buf][dir][row][k] activation hi
__device__ __align__(16) __half g_Alo[2][2][BS][KTOT];  // activation lo (fp32 residual)
__device__ __align__(16) float g_bias[2][G4];           // gate-interleaved bias
__device__ __align__(16) float g_h[2][2][BS][HID];      // fp32 h for head [buf][dir]
__device__ __align__(16) float g_c[2][BS][HID];         // cell state [dir]
__device__ u64 g_arrive;                                // grid barrier counter (h ready)
__device__ u64 g_xarrive;                               // producer flag (x_next ready)

// ---------------- helpers --------------------------------------------------
__device__ __forceinline__ void unpack2(u64 v, float& lo, float& hi) {
    asm("mov.b64 {%0, %1}, %2;" : "=f"(lo), "=f"(hi) : "l"(v));
}
__device__ __forceinline__ void fma2(u64& d, u64 a, u64 b) {
    asm("fma.rn.f32x2 %0, %1, %2, %0;" : "+l"(d) : "l"(a), "l"(b));
}
__device__ __forceinline__ u32 smem_u32(const void* p) {
    u32 a; asm("{ .reg .u64 t; cvta.to.shared.u64 t, %1; cvt.u32.u64 %0, t; }" : "=r"(a) : "l"(p));
    return a;
}

#define SW128(x) ((x) ^ (((x) >> 3) & 0x70))

#define CP16(dst, src) \
    asm volatile("cp.async.cg.shared.global [%0], [%1], 16;" :: "r"(dst), "l"(src))
#define CP_COMMIT() asm volatile("cp.async.commit_group;" ::: "memory")
#define CP_WAIT(n)  asm volatile("cp.async.wait_group %0;" :: "n"(n) : "memory")

#define LDSM4(R, A)                                                          \
    asm volatile("ldmatrix.sync.aligned.m8n8.x4.shared.b16 {%0,%1,%2,%3}, [%4];" \
                 : "=r"((R)[0]), "=r"((R)[1]), "=r"((R)[2]), "=r"((R)[3])    \
                 : "r"(A))

#define MMA16816(D, A, B0, B1)                                               \
    asm volatile("mma.sync.aligned.m16n8k16.row.col.f32.f16.f16.f32 "        \
                 "{%0,%1,%2,%3}, {%4,%5,%6,%7}, {%8,%9}, {%0,%1,%2,%3};"     \
                 : "+f"((D)[0]), "+f"((D)[1]), "+f"((D)[2]), "+f"((D)[3])    \
                 : "r"((A)[0]), "r"((A)[1]), "r"((A)[2]), "r"((A)[3]),       \
                   "r"(B0), "r"(B1))

// Fence-free grid barrier (h visibility). Release via atom.add.release.gpu;
// acquire via leader ld.acquire.gpu poll. No CCTL.IVALL: all cross-block
// reads bypass L1 (cp.async.cg / __ldcg).
__device__ __forceinline__ void grid_sync(u64 target) {
    __syncthreads();
    if (threadIdx.x == 0) {
        u64 old;
        asm volatile("atom.add.release.gpu.u64 %0, [%1], 1;"
                     : "=l"(old) : "l"(&g_arrive) : "memory");
        u64 v;
        do {
            asm volatile("ld.acquire.gpu.u64 %0, [%1];"
                         : "=l"(v) : "l"(&g_arrive) : "memory");
        } while (v < target);
    }
    __syncthreads();
}

// fast nonlinearities (MUFU-based; rel err ~1e-6)
__device__ __forceinline__ float fast_sigmoid(float x) {
    return __fdividef(1.f, 1.f + __expf(-x));
}
__device__ __forceinline__ float fast_tanh(float x) {
    return 1.f - __fdividef(2.f, 1.f + __expf(2.f * x));
}

// smem: 3 stages of 40 KB. Stage layout: Ah 16K | Al 16K | W 8K
#define STG    40960
#define OFF_AL 16384
#define OFF_W  32768
#define DYN_SMEM (3 * STG)

// ---------------------------------------------------------------------------
// prep: gate-interleave weights (fp16) into unified-K layout; split
// activations to fp16 hi/lo; init h, c, barriers.
// reordered row r -> orig row (r&3)*HID + (r>>2); K: [0,512)=Wih, [512,1536)=Whh
// ---------------------------------------------------------------------------
__global__ void prep_kernel(const float* __restrict__ Wih_f, const float* __restrict__ Whh_f,
                            const float* __restrict__ b_f,
                            const float* __restrict__ Wih_b, const float* __restrict__ Whh_b,
                            const float* __restrict__ b_b,
                            const float* __restrict__ dec) {
    int idx = blockIdx.x * blockDim.x + threadIdx.x;
    int stride = gridDim.x * blockDim.x;
    if (idx == 0) { g_arrive = 0ULL; g_xarrive = 0ULL; }

    for (int i = idx; i < 2 * G4 * KTOT; i += stride) {
        int dir = i / (G4 * KTOT);
        int rem = i - dir * (G4 * KTOT);
        int r = rem / KTOT, k = rem - r * KTOT;
        int orow = (r & 3) * HID + (r >> 2);
        float w;
        if (k < LATENT) w = (dir ? Wih_b : Wih_f)[orow * LATENT + k];
        else            w = (dir ? Whh_b : Whh_f)[orow * HID + (k - LATENT)];
        g_W[dir][r][k] = __float2half_rn(w);
    }
    for (int i = idx; i < 2 * G4; i += stride) {
        int dir = i / G4, r = i - dir * G4;
        g_bias[dir][r] = (dir ? b_b : b_f)[(r & 3) * HID + (r >> 2)];
    }
    for (int i = idx; i < 2 * 2 * BS * KTOT; i += stride) {
        int buf = i / (2 * BS * KTOT);
        int rem = i - buf * (2 * BS * KTOT);
        int dir = rem / (BS * KTOT);
        int rem2 = rem - dir * (BS * KTOT);
        int row = rem2 / KTOT, k = rem2 - row * KTOT;
        float v = (buf == 0 && k < LATENT) ? dec[row * LATENT + k] : 0.f;
        __half hi = __float2half_rn(v);
        __half lo = __float2half_rn(v - __half2float(hi));
        g_Ahi[buf][dir][row][k] = hi;
        g_Alo[buf][dir][row][k] = lo;
    }
    for (int i = idx; i < 2 * 2 * BS * HID; i += stride) ((float*)g_h)[i] = 0.f;
    for (int i = idx; i < 2 * BS * HID; i += stride)     ((float*)g_c)[i] = 0.f;
}

// ---------------------------------------------------------------------------
// persistent kernel: 128 blocks x 256 threads, one launch for all T steps.
// phase A: block = (dir, 64 gate-cols); 4x2 warp grid, warp tile 32(M)x32(N).
//          fp16 2-term split mma.sync; cp.async 3-stage ring; K-chunks ordered
//          h-part first so the x-part wait (producer flag) lands ~2/3 in.
// phase B: head (x_next GEMM + fc1) — overlapped with next step's phase A
//          via g_xarrive flag instead of a second grid barrier.
// ---------------------------------------------------------------------------
__global__ void __launch_bounds__(NTHR, 1) lstm_persist(
        int T, float* __restrict__ out,
        const float* __restrict__ W_out, const float* __restrict__ b_out,
        const float* __restrict__ W_fc1, const float* __restrict__ b_fc1) {

    extern __shared__ __align__(16) unsigned char dsm[];
    const u32 smem_base = smem_u32(dsm);

    const int tid = threadIdx.x;
    const int bid = blockIdx.x;
    const int wid = tid >> 5;
    const int lane = tid & 31;

    const int dir = bid >> 6;
    const int colbase = (bid & 63) << 6;

    // warp tile mapping: 4 warps along M (32 rows), 2 along N (32 cols)
    const int wm = wid & 3;
    const int wn = wid >> 2;
    const int R0 = wm * 32;
    const int C0 = wn * 32;

    // ldmatrix per-lane constants
    const int arow = lane & 15;
    const u32 khA = (u32)(lane >> 4) * 16;
    const int brow = (lane & 7) + ((lane >> 4) & 1) * 8;
    const u32 khB = (u32)((lane >> 3) & 1) * 16;
    const u32 swA = (u32)(arow & 7) << 4;
    const u32 swB = (u32)(brow & 7) << 4;
    const u32 aRowOff0 = (u32)(R0 + arow) * 128;
    const u32 aRowOff1 = (u32)(R0 + 16 + arow) * 128;
    const u32 bRowOff0 = OFF_W + (u32)(C0 + brow) * 128;
    const u32 bRowOff1 = OFF_W + (u32)(C0 + 16 + brow) * 128;

    // cp.async per-thread source/dest precompute
    u32 cpdstA[4], cpdstW[2];
    int cprowA[4], cpqA[4], cprowW[2], cpqW[2];
#pragma unroll
    for (int i = 0; i < 4; i++) {
        int p = tid + i * NTHR, row = p >> 3, q = p & 7;
        cprowA[i] = row; cpqA[i] = q;
        cpdstA[i] = SW128((u32)(row * 128 + q * 16));
    }
#pragma unroll
    for (int i = 0; i < 2; i++) {
        int p = tid + i * NTHR, row = p >> 3, q = p & 7;
        cprowW[i] = row; cpqW[i] = q;
        cpdstW[i] = SW128((u32)(row * 128 + q * 16));
    }

    // head mapping
    const int bt = bid >> 3;   // 16 row-tiles of 8
    const int lt = bid & 7;    // 8 latent col-tiles of 64
    float* s_hb_f = (float*)dsm;   // segmented layout: r*ROWF + seg*SEGF + within

    for (int t = 0; t < T; t++) {
        const int cur = t & 1;
        const int nxt = cur ^ 1;
        const __half* __restrict__ Ah = &g_Ahi[cur][dir][0][0];
        const __half* __restrict__ Al = &g_Alo[cur][dir][0][0];
        const __half* __restrict__ Wp = &g_W[dir][colbase][0];
        const u64 xtarget = (u64)t * NBLK;   // phase B(t-1) arrivals gate x(t)

#define ISSUE_CHUNK(cc, st)                                                   \
        {                                                                      \
            const u32 sb = smem_base + (u32)(st) * STG;                        \
            const size_t c64 = (size_t)(cc) * CHK;                             \
            _Pragma("unroll")                                                  \
            for (int i = 0; i < 4; i++) {                                      \
                const char* s  = (const char*)(Ah + (size_t)cprowA[i] * KTOT + c64) + cpqA[i] * 16; \
                const char* s2 = (const char*)(Al + (size_t)cprowA[i] * KTOT + c64) + cpqA[i] * 16; \
                CP16(sb + cpdstA[i], s);                                       \
                CP16(sb + OFF_AL + cpdstA[i], s2);                             \
            }                                                                  \
            _Pragma("unroll")                                                  \
            for (int i = 0; i < 2; i++) {                                      \
                const char* s = (const char*)(Wp + (size_t)cprowW[i] * KTOT + c64) + cpqW[i] * 16; \
                CP16(sb + OFF_W + cpdstW[i], s);                               \
            }                                                                  \
            CP_COMMIT();                                                       \
        }

        // ================= phase A: fp16 2-term HMMA pipeline ==============
        float acc[2][4][4];
#pragma unroll
        for (int mt = 0; mt < 2; mt++)
#pragma unroll
            for (int nt = 0; nt < 4; nt++)
#pragma unroll
                for (int i = 0; i < 4; i++) acc[mt][nt][i] = 0.f;

        ISSUE_CHUNK(MAPC(0), 0);   // first h-chunk (no x dependency)

        int stage = 0;
#pragma unroll 1
        for (int c = 0; c < NCHUNK; c++) {
            if (c + 1 < NCHUNK) {
                if (c + 1 == 16) {
                    // about to issue first x-chunk: wait for all phase B(t-1)
                    if (tid == 0) {
                        u64 v;
                        do {
                            asm volatile("ld.acquire.gpu.u64 %0, [%1];"
                                         : "=l"(v) : "l"(&g_xarrive) : "memory");
                        } while (v < xtarget);
                    }
                    __syncthreads();
                }
                const int nstage = (stage == 2) ? 0 : stage + 1;
                ISSUE_CHUNK(MAPC(c + 1), nstage);
                CP_WAIT(1);          // chunk c complete (c+1 may be in flight)
            } else {
                CP_WAIT(0);
            }
            __syncthreads();         // chunk c visible; ring period 3 protects reuse

            const u32 sb = smem_base + (u32)stage * STG;
            const u32 a0 = sb + aRowOff0, a1 = sb + aRowOff1;
            const u32 b0 = sb + bRowOff0, b1 = sb + bRowOff1;

#pragma unroll
            for (int kk = 0; kk < 4; kk++) {
                const u32 xA = ((u32)(kk * 32) + khA) ^ swA;
                const u32 xB = ((u32)(kk * 32) + khB) ^ swB;
                u32 ah[2][4], al[2][4], bw[2][4];
                LDSM4(ah[0], a0 + xA);
                LDSM4(ah[1], a1 + xA);
                LDSM4(al[0], a0 + OFF_AL + xA);
                LDSM4(al[1], a1 + OFF_AL + xA);
                LDSM4(bw[0], b0 + xB);
                LDSM4(bw[1], b1 + xB);
#pragma unroll
                for (int mt = 0; mt < 2; mt++)
#pragma unroll
                    for (int np = 0; np < 2; np++)
#pragma unroll
                        for (int hf = 0; hf < 2; hf++) {
                            const int nt = np * 2 + hf;
                            MMA16816(acc[mt][nt], ah[mt], bw[np][2 * hf], bw[np][2 * hf + 1]);
                            MMA16816(acc[mt][nt], al[mt], bw[np][2 * hf], bw[np][2 * hf + 1]);
                        }
            }
            stage = (stage == 2) ? 0 : stage + 1;
        }

        // -------- epilogue: pair-exchange quads, LSTM cell, write h --------
#pragma unroll
        for (int mt = 0; mt < 2; mt++)
#pragma unroll
            for (int nt = 0; nt < 4; nt++) {
                float d0 = acc[mt][nt][0], d1 = acc[mt][nt][1];
                float d2 = acc[mt][nt][2], d3 = acc[mt][nt][3];
                float p0 = __shfl_xor_sync(0xffffffffu, d0, 1);
                float p1 = __shfl_xor_sync(0xffffffffu, d1, 1);
                float p2 = __shfl_xor_sync(0xffffffffu, d2, 1);
                float p3 = __shfl_xor_sync(0xffffffffu, d3, 1);
                if (!(lane & 1)) {
                    const int q = (lane >> 1) & 1;
                    const int col4 = colbase + C0 + nt * 8 + q * 4;
                    const int jp = col4 >> 2;
                    const float4 b4 = *(const float4*)&g_bias[dir][col4];
                    const int r0 = R0 + mt * 16 + (lane >> 2);
#pragma unroll
                    for (int rr = 0; rr < 2; rr++) {
                        const int row = r0 + rr * 8;
                        float zi = (rr ? d2 : d0) + b4.x;
                        float zf = (rr ? d3 : d1) + b4.y;
                        float zg = (rr ? p2 : p0) + b4.z;
                        float zo = (rr ? p3 : p1) + b4.w;
                        float si = fast_sigmoid(zi);
                        float sf = fast_sigmoid(zf);
                        float so = fast_sigmoid(zo);
                        float c2 = sf * g_c[dir][row][jp] + si * fast_tanh(zg);
                        g_c[dir][row][jp] = c2;
                        float hv = so * fast_tanh(c2);
                        g_h[nxt][dir][row][jp] = hv;
                        __half hhi = __float2half_rn(hv);
                        __half hlo = __float2half_rn(hv - __half2float(hhi));
                        g_Ahi[nxt][dir][row][LATENT + jp] = hhi;
                        g_Alo[nxt][dir][row][LATENT + jp] = hlo;
                    }
                }
            }

        grid_sync((u64)(t + 1) * NBLK);   // h(t) globally visible

        // ================= phase B: head (overlapped with next phase A) ====
        for (int i = tid; i < 8 * 256; i += NTHR) {
            int r = i >> 8;               // 0..7
            int k = (i & 255) * 4;        // 0..1020
            float4 v = __ldcg((const float4*)&g_h[nxt][1][bt * 8 + r][k]);
            *(float4*)&s_hb_f[r * ROWF + (k >> 8) * SEGF + (k & 255)] = v;
        }
        __syncthreads();

        // x_next = hb @ W_out^T + b_out, split to fp16 hi/lo for both dirs
        {
            const int l_loc = tid >> 2;
            const int q = tid & 3;
            const int l = lt * 64 + l_loc;
            const ulonglong2* __restrict__ wp2 =
                (const ulonglong2*)(W_out + (size_t)l * HID) + q * 64;
            const u64* __restrict__ hp = (const u64*)dsm + q * (SEGF / 2);
            u64 hacc[8];
#pragma unroll
            for (int r = 0; r < 8; r++) hacc[r] = 0ull;
#pragma unroll 2
            for (int k4 = 0; k4 < 64; k4++) {
                ulonglong2 ww = wp2[k4];
#pragma unroll
                for (int r = 0; r < 8; r++) {
                    fma2(hacc[r], ww.x, hp[r * (ROWF / 2) + 2 * k4]);
                    fma2(hacc[r], ww.y, hp[r * (ROWF / 2) + 2 * k4 + 1]);
                }
            }
#pragma unroll
            for (int r = 0; r < 8; r++) {
                float lo, hi; unpack2(hacc[r], lo, hi);
                float s = lo + hi;
                s += __shfl_xor_sync(0xffffffffu, s, 1);
                s += __shfl_xor_sync(0xffffffffu, s, 2);
                if (q == 0) {
                    float xv = s + b_out[l];
                    int row = bt * 8 + r;
                    __half xh = __float2half_rn(xv);
                    __half xl = __float2half_rn(xv - __half2float(xh));
                    g_Ahi[nxt][0][row][l] = xh;
                    g_Ahi[nxt][1][row][l] = xh;
                    g_Alo[nxt][0][row][l] = xl;
                    g_Alo[nxt][1][row][l] = xl;
                }
            }
        }

        // out[b, t] = relu(concat(hf,hb)) . W_fc1 + b_fc1   (lt==0 blocks)
        if (lt == 0) {
            const int r = tid >> 5, ln = tid & 31;
            const int b = bt * 8 + r;
            const float* __restrict__ hf = &g_h[nxt][0][b][0];
            float facc = 0.f;
            for (int k = ln * 4; k < HID; k += 128) {
                float4 f   = __ldcg((const float4*)&hf[k]);
                float4 wf  = *(const float4*)&W_fc1[k];
                float4 hb4 = *(const float4*)&s_hb_f[r * ROWF + (k >> 8) * SEGF + (k & 255)];
                float4 wb  = *(const float4*)&W_fc1[HID + k];
                facc += fmaxf(f.x, 0.f) * wf.x + fmaxf(f.y, 0.f) * wf.y
                      + fmaxf(f.z, 0.f) * wf.z + fmaxf(f.w, 0.f) * wf.w
                      + fmaxf(hb4.x, 0.f) * wb.x + fmaxf(hb4.y, 0.f) * wb.y
                      + fmaxf(hb4.z, 0.f) * wb.z + fmaxf(hb4.w, 0.f) * wb.w;
            }
#pragma unroll
            for (int off = 16; off; off >>= 1)
                facc += __shfl_xor_sync(0xffffffffu, facc, off);
            if (ln == 0) out[(size_t)b * T + t] = facc + b_fc1[0];
        }

        // block-local completion of phase B: s_hb reads done before next
        // step's cp.async overwrites dsm; then announce x(t+1) ready.
        __syncthreads();
        if (tid == 0) {
            u64 old;
            asm volatile("atom.add.release.gpu.u64 %0, [%1], 1;"
                         : "=l"(old) : "l"(&g_xarrive) : "memory");
        }
    }
}

// ---------------------------------------------------------------------------
extern "C" void kernel_launch(void* const* d_in, const int* in_sizes, int n_in,
                              void* d_out, int out_size) {
    const float* dec   = (const float*)d_in[0];
    // d_in[1] = lengths (T derives from out_size)
    const float* Wih_f = (const float*)d_in[2];
    const float* Whh_f = (const float*)d_in[3];
    const float* b_f   = (const float*)d_in[4];
    const float* Wih_b = (const float*)d_in[5];
    const float* Whh_b = (const float*)d_in[6];
    const float* b_b   = (const float*)d_in[7];
    const float* W_out = (const float*)d_in[8];
    const float* b_out = (const float*)d_in[9];
    const float* W_fc1 = (const float*)d_in[10];
    const float* b_fc1 = (const float*)d_in[11];
    float* out = (float*)d_out;

    const int T = out_size / BS;

    cudaFuncSetAttribute(lstm_persist, cudaFuncAttributeMaxDynamicSharedMemorySize, DYN_SMEM);

    prep_kernel<<<1024, 256>>>(Wih_f, Whh_f, b_f, Wih_b, Whh_b, b_b, dec);
    if (T > 0) {
        lstm_persist<<<NBLK, NTHR, DYN_SMEM>>>(T, out, W_out, b_out, W_fc1, b_fc1);
    }
}